// round 4
// baseline (speedup 1.0000x reference)
#include <cuda_runtime.h>
#include <cuda_bf16.h>

// ============================================================================
// AutoInt multi-head attention — fp32 with packed FFMA2 (fma.rn.f32x2).
// B=4096, F=40, E=64, H=4, A=64. One CTA per batch, 256 threads, 2 CTAs/SM.
//
// Round-2 changes vs round-1 (which was L1TEX/crossbar-bound at 90.6%):
//  * Warp mapping: warp owns 8 columns x all 40 rows (lane = rowgrp*4+colgrp)
//    -> A loads are 8-address broadcasts (1 wavefront), B loads 4-address
//    broadcasts (1 wavefront), no cross-warp B re-read blowup.
//  * All "A" matrices stored DUPLICATED ({a,a} pairs) in smem so packed
//    fma.rn.f32x2 needs zero pack instructions: LDS.128 yields two packed
//    A operands (k, k+1); B pairs load as LDS.64 directly.
//  * scores = X (Wq Wk^T) X^T with M precomputed (19% FLOP cut, unchanged).
// ============================================================================

#define B_DIM 4096
#define F_DIM 40
#define E_DIM 64
#define A_DIM 64
#define H_DIM 4

typedef unsigned long long ULL;

// ---- shared memory layout (floats) ----------------------------------------
#define XSD_LD 132   // X duplicated: [40][128] (+pad), 16B-aligned rows
#define XST_LD 44    // X^T: [64][40] (+pad)
#define TSD_LD 132   // t duplicated: [40][128]
#define VS_LD  68    // v: [40][64] (+pad)
#define PSD_LD 88    // attn duplicated: [40][80] (+pad)

#define OFF_XSD 0
#define OFF_XST (OFF_XSD + F_DIM * XSD_LD)      // 5280
#define OFF_WA  (OFF_XST + E_DIM * XST_LD)      // 8096
#define OFF_WB  (OFF_WA + 64 * 64)              // 12192
#define OFF_TSD (OFF_WB + 64 * 64)              // 16288
#define OFF_VS  (OFF_TSD + F_DIM * TSD_LD)      // 21568
#define OFF_PSD (OFF_VS + F_DIM * VS_LD)        // 24288
#define SMEM_FLOATS (OFF_PSD + F_DIM * PSD_LD)  // 27808
#define SMEM_BYTES  (SMEM_FLOATS * 4)           // 111232 B -> 2 CTAs/SM

__device__ float g_M[H_DIM * E_DIM * E_DIM];    // M_h = Wq_h @ Wk_h^T

// ---- packed f32x2 helpers ---------------------------------------------------
__device__ __forceinline__ void fma2(ULL& acc, ULL a, ULL b) {
    asm("fma.rn.f32x2 %0, %1, %2, %3;" : "=l"(acc) : "l"(a), "l"(b), "l"(acc));
}
__device__ __forceinline__ float2 unpack2(ULL v) {
    float2 r;
    asm("mov.b64 {%0, %1}, %2;" : "=f"(r.x), "=f"(r.y) : "l"(v));
    return r;
}

// ----------------------------------------------------------------------------
__global__ void precompute_M_kernel(const float* __restrict__ Wq,
                                    const float* __restrict__ Wk) {
    int h = blockIdx.x;
    __shared__ float sq[E_DIM * A_DIM];
    __shared__ float sk[E_DIM * A_DIM];
    const float* wq = Wq + h * E_DIM * A_DIM;
    const float* wk = Wk + h * E_DIM * A_DIM;
    for (int i = threadIdx.x; i < E_DIM * A_DIM; i += 256) {
        sq[i] = wq[i];
        sk[i] = wk[i];
    }
    __syncthreads();
    for (int idx = threadIdx.x; idx < E_DIM * E_DIM; idx += 256) {
        int e  = idx >> 6;
        int ep = idx & 63;
        float s = 0.f;
        #pragma unroll 8
        for (int a = 0; a < A_DIM; a++)
            s = fmaf(sq[e * A_DIM + a], sk[ep * A_DIM + a], s);
        g_M[h * E_DIM * E_DIM + idx] = s;
    }
}

// ----------------------------------------------------------------------------
__global__ void __launch_bounds__(256, 2)
attn_main_kernel(const float* __restrict__ Xg,
                 const float* __restrict__ Wv,
                 const float* __restrict__ Wres,
                 float* __restrict__ out) {
    extern __shared__ float sm[];
    float* XSD = sm + OFF_XSD;
    float* XST = sm + OFF_XST;
    float* WA  = sm + OFF_WA;
    float* WB  = sm + OFF_WB;
    float* TSD = sm + OFF_TSD;
    float* VS  = sm + OFF_VS;
    float* PSD = sm + OFF_PSD;

    const int tid  = threadIdx.x;
    const int b    = blockIdx.x;
    const int w    = tid >> 5;
    const int lane = tid & 31;
    const int rg   = lane >> 2;          // row group: rows rg, rg+8, ..., rg+32
    const int cg   = lane & 3;           // col-pair within warp
    const int p    = w * 4 + cg;         // global col-pair 0..31 -> cols 2p,2p+1

    const float* xb = Xg + (size_t)b * (F_DIM * E_DIM);

    // ---- load X into XSD (duplicated) and XST (transposed) ----
    for (int i = tid; i < F_DIM * E_DIM / 4; i += 256) {
        float4 v = reinterpret_cast<const float4*>(xb)[i];
        int f  = i >> 4;
        int e4 = (i & 15) * 4;
        float4* d = reinterpret_cast<float4*>(XSD + f * XSD_LD + 2 * e4);
        d[0] = make_float4(v.x, v.x, v.y, v.y);
        d[1] = make_float4(v.z, v.z, v.w, v.w);
        XST[(e4 + 0) * XST_LD + f] = v.x;
        XST[(e4 + 1) * XST_LD + f] = v.y;
        XST[(e4 + 2) * XST_LD + f] = v.z;
        XST[(e4 + 3) * XST_LD + f] = v.w;
    }

    for (int h = 0; h < H_DIM; h++) {
        __syncthreads();   // protect WA/WB (+ XSD/XST on first iter)

        // ---- stage WA = M_h, WB = Wv_h ----
        {
            const float4* msrc = reinterpret_cast<const float4*>(g_M + h * 4096);
            const float4* vsrc = reinterpret_cast<const float4*>(Wv + h * 4096);
            for (int i = tid; i < 1024; i += 256) {
                reinterpret_cast<float4*>(WA)[i] = msrc[i];
                reinterpret_cast<float4*>(WB)[i] = vsrc[i];
            }
        }
        __syncthreads();

        // ---- GEMM1: TS = X @ M_h, VS = X @ Wv_h (K=64, packed) ----
        {
            ULL ts[5] = {0, 0, 0, 0, 0};
            ULL vs[5] = {0, 0, 0, 0, 0};
            #pragma unroll 4
            for (int k2 = 0; k2 < 32; k2++) {
                int k = 2 * k2;
                ULL bA0 = *reinterpret_cast<const ULL*>(WA + k * 64 + 2 * p);
                ULL bA1 = *reinterpret_cast<const ULL*>(WA + k * 64 + 64 + 2 * p);
                ULL bB0 = *reinterpret_cast<const ULL*>(WB + k * 64 + 2 * p);
                ULL bB1 = *reinterpret_cast<const ULL*>(WB + k * 64 + 64 + 2 * p);
                #pragma unroll
                for (int i = 0; i < 5; i++) {
                    ulonglong2 a = *reinterpret_cast<const ulonglong2*>(
                        XSD + (rg + 8 * i) * XSD_LD + 2 * k);
                    fma2(ts[i], a.x, bA0);
                    fma2(ts[i], a.y, bA1);
                    fma2(vs[i], a.x, bB0);
                    fma2(vs[i], a.y, bB1);
                }
            }
            #pragma unroll
            for (int i = 0; i < 5; i++) {
                int r = rg + 8 * i;
                float2 t = unpack2(ts[i]);
                float2 v = unpack2(vs[i]);
                *reinterpret_cast<float4*>(TSD + r * TSD_LD + 4 * p) =
                    make_float4(t.x, t.x, t.y, t.y);           // duplicated
                *reinterpret_cast<float2*>(VS + r * VS_LD + 2 * p) =
                    make_float2(v.x, v.y);                     // scalar
            }
        }
        __syncthreads();

        // ---- PS = TS @ X^T (K=64, packed), warps 0-4; warps 5-7 stage Wres ----
        if (w < 5) {
            int q = p;                       // col-pair 0..19 -> cols 2q,2q+1
            ULL ps[5] = {0, 0, 0, 0, 0};
            #pragma unroll 4
            for (int k2 = 0; k2 < 32; k2++) {
                int k = 2 * k2;
                ULL b0 = *reinterpret_cast<const ULL*>(XST + k * XST_LD + 2 * q);
                ULL b1 = *reinterpret_cast<const ULL*>(XST + (k + 1) * XST_LD + 2 * q);
                #pragma unroll
                for (int i = 0; i < 5; i++) {
                    ulonglong2 a = *reinterpret_cast<const ulonglong2*>(
                        TSD + (rg + 8 * i) * TSD_LD + 2 * k);
                    fma2(ps[i], a.x, b0);
                    fma2(ps[i], a.y, b1);
                }
            }
            #pragma unroll
            for (int i = 0; i < 5; i++) {
                float2 s = unpack2(ps[i]);
                *reinterpret_cast<float4*>(PSD + (rg + 8 * i) * PSD_LD + 4 * q) =
                    make_float4(s.x, s.x, s.y, s.y);           // duplicated
            }
        } else {
            // stage WA <- Wres[:, h*64:(h+1)*64]   (WA free after GEMM1)
            for (int i = tid - 160; i < 1024; i += 96) {
                int e  = i >> 4;
                int c4 = i & 15;
                reinterpret_cast<float4*>(WA + e * 64)[c4] =
                    *reinterpret_cast<const float4*>(Wres + e * 256 + h * 64 + 4 * c4);
            }
        }
        __syncthreads();

        // ---- softmax over rows of PSD (duplicated layout, stride 2) ----
        {
            #pragma unroll
            for (int j = 0; j < 5; j++) {
                int r = w + 8 * j;
                float v1 = PSD[r * PSD_LD + 2 * lane];
                float v2 = (lane < 8) ? PSD[r * PSD_LD + 2 * (32 + lane)] : -3.4e38f;
                float m = fmaxf(v1, v2);
                #pragma unroll
                for (int o = 16; o; o >>= 1)
                    m = fmaxf(m, __shfl_xor_sync(0xffffffffu, m, o));
                float e1 = __expf(v1 - m);
                float e2 = (lane < 8) ? __expf(v2 - m) : 0.f;
                float s = e1 + e2;
                #pragma unroll
                for (int o = 16; o; o >>= 1)
                    s += __shfl_xor_sync(0xffffffffu, s, o);
                float inv = 1.f / s;
                float q1 = e1 * inv;
                *reinterpret_cast<float2*>(PSD + r * PSD_LD + 2 * lane) =
                    make_float2(q1, q1);
                if (lane < 8) {
                    float q2 = e2 * inv;
                    *reinterpret_cast<float2*>(PSD + r * PSD_LD + 2 * (32 + lane)) =
                        make_float2(q2, q2);
                }
            }
        }
        __syncthreads();

        // ---- out = attn @ VS (K=40) + X @ WresBlk (K=64), packed; relu; store
        {
            ULL acc[5] = {0, 0, 0, 0, 0};
            #pragma unroll 4
            for (int k2 = 0; k2 < 20; k2++) {          // attn @ VS
                int k = 2 * k2;
                ULL b0 = *reinterpret_cast<const ULL*>(VS + k * VS_LD + 2 * p);
                ULL b1 = *reinterpret_cast<const ULL*>(VS + (k + 1) * VS_LD + 2 * p);
                #pragma unroll
                for (int i = 0; i < 5; i++) {
                    ulonglong2 a = *reinterpret_cast<const ulonglong2*>(
                        PSD + (rg + 8 * i) * PSD_LD + 2 * k);
                    fma2(acc[i], a.x, b0);
                    fma2(acc[i], a.y, b1);
                }
            }
            #pragma unroll 4
            for (int k2 = 0; k2 < 32; k2++) {          // residual
                int k = 2 * k2;
                ULL b0 = *reinterpret_cast<const ULL*>(WA + k * 64 + 2 * p);
                ULL b1 = *reinterpret_cast<const ULL*>(WA + k * 64 + 64 + 2 * p);
                #pragma unroll
                for (int i = 0; i < 5; i++) {
                    ulonglong2 a = *reinterpret_cast<const ulonglong2*>(
                        XSD + (rg + 8 * i) * XSD_LD + 2 * k);
                    fma2(acc[i], a.x, b0);
                    fma2(acc[i], a.y, b1);
                }
            }
            float* ob = out + (size_t)b * (F_DIM * 256) + h * 64 + 2 * p;
            #pragma unroll
            for (int i = 0; i < 5; i++) {
                int f = rg + 8 * i;
                float2 r = unpack2(acc[i]);
                *reinterpret_cast<float2*>(ob + f * 256) =
                    make_float2(fmaxf(r.x, 0.f), fmaxf(r.y, 0.f));
            }
        }
    }
}

// ----------------------------------------------------------------------------
extern "C" void kernel_launch(void* const* d_in, const int* in_sizes, int n_in,
                              void* d_out, int out_size) {
    const float* X    = (const float*)d_in[0];
    const float* Wq   = (const float*)d_in[1];
    const float* Wk   = (const float*)d_in[2];
    const float* Wv   = (const float*)d_in[3];
    const float* Wres = (const float*)d_in[4];
    float* out = (float*)d_out;

    cudaFuncSetAttribute(attn_main_kernel,
                         cudaFuncAttributeMaxDynamicSharedMemorySize, SMEM_BYTES);

    precompute_M_kernel<<<H_DIM, 256>>>(Wq, Wk);
    attn_main_kernel<<<B_DIM, 256, SMEM_BYTES>>>(X, Wv, Wres, out);
}

// round 5
// speedup vs baseline: 1.3865x; 1.3865x over previous
#include <cuda_runtime.h>
#include <cuda_bf16.h>

// ============================================================================
// AutoInt MHA — fp32 FFMA2, round 5.
// Fix vs round 2-4 (L1TEX 92.8% bound): crossbar cost = bytes DELIVERED, so
//  * A matrices (X, T, attn) stored SCALAR; {a,a} pairs built with 1 MOV each
//    (ALU/issue had headroom) -> A smem traffic halved.
//  * Residual fused into GEMM1 as 3rd output sharing A loads; result parked
//    in RS, re-added in epilogue. GEMM3 is attn@V only.
// One CTA/batch, 256 thr, 2 CTA/SM. scores = X (Wq Wk^T) X^T, M precomputed.
// ============================================================================

#define B_DIM 4096
#define F_DIM 40
#define E_DIM 64
#define A_DIM 64
#define H_DIM 4

typedef unsigned long long ULL;

#define XS_LD  68
#define XST_LD 44
#define TS_LD  68
#define VS_LD  68
#define RS_LD  68
#define PS_LD  44

#define OFF_XS  0
#define OFF_XST (OFF_XS  + F_DIM * XS_LD)    // 2720
#define OFF_WA  (OFF_XST + E_DIM * XST_LD)   // 5536
#define OFF_WB  (OFF_WA  + 4096)             // 9632
#define OFF_WC  (OFF_WB  + 4096)             // 13728
#define OFF_TS  (OFF_WC  + 4096)             // 17824
#define OFF_VS  (OFF_TS  + F_DIM * TS_LD)    // 20544
#define OFF_RS  (OFF_VS  + F_DIM * VS_LD)    // 23264
#define OFF_PS  (OFF_RS  + F_DIM * RS_LD)    // 25984
#define SMEM_FLOATS (OFF_PS + F_DIM * PS_LD) // 27744
#define SMEM_BYTES  (SMEM_FLOATS * 4)        // 110976 -> 2 CTAs/SM

__device__ float g_M[H_DIM * E_DIM * E_DIM];

// ---- packed helpers --------------------------------------------------------
__device__ __forceinline__ void fma2(ULL& acc, ULL a, ULL b) {
    asm("fma.rn.f32x2 %0, %1, %2, %0;" : "+l"(acc) : "l"(a), "l"(b));
}
__device__ __forceinline__ ULL dup2(float f) {
    ULL r;
    asm("mov.b64 %0, {%1, %1};" : "=l"(r) : "f"(f));
    return r;
}
__device__ __forceinline__ float2 unpack2(ULL v) {
    float2 r;
    asm("mov.b64 {%0, %1}, %2;" : "=f"(r.x), "=f"(r.y) : "l"(v));
    return r;
}
__device__ __forceinline__ ULL add2(ULL a, ULL b) {
    ULL r;
    asm("add.rn.f32x2 %0, %1, %2;" : "=l"(r) : "l"(a), "l"(b));
    return r;
}

// ----------------------------------------------------------------------------
__global__ void precompute_M_kernel(const float* __restrict__ Wq,
                                    const float* __restrict__ Wk) {
    int h = blockIdx.x;
    __shared__ float sq[E_DIM * A_DIM];
    __shared__ float sk[E_DIM * A_DIM];
    const float* wq = Wq + h * E_DIM * A_DIM;
    const float* wk = Wk + h * E_DIM * A_DIM;
    for (int i = threadIdx.x; i < E_DIM * A_DIM; i += 256) {
        sq[i] = wq[i];
        sk[i] = wk[i];
    }
    __syncthreads();
    for (int idx = threadIdx.x; idx < E_DIM * E_DIM; idx += 256) {
        int e  = idx >> 6;
        int ep = idx & 63;
        float s = 0.f;
        #pragma unroll 8
        for (int a = 0; a < A_DIM; a++)
            s = fmaf(sq[e * A_DIM + a], sk[ep * A_DIM + a], s);
        g_M[h * E_DIM * E_DIM + idx] = s;
    }
}

// ----------------------------------------------------------------------------
__global__ void __launch_bounds__(256, 2)
attn_main_kernel(const float* __restrict__ Xg,
                 const float* __restrict__ Wv,
                 const float* __restrict__ Wres,
                 float* __restrict__ out) {
    extern __shared__ float sm[];
    float* XS  = sm + OFF_XS;
    float* XST = sm + OFF_XST;
    float* WA  = sm + OFF_WA;
    float* WB  = sm + OFF_WB;
    float* WC  = sm + OFF_WC;
    float* TS  = sm + OFF_TS;
    float* VS  = sm + OFF_VS;
    float* RS  = sm + OFF_RS;
    float* PS  = sm + OFF_PS;

    const int tid  = threadIdx.x;
    const int b    = blockIdx.x;
    const int w    = tid >> 5;
    const int lane = tid & 31;
    const int rg   = lane >> 2;          // rows rg, rg+8, ..., rg+32
    const int cg   = lane & 3;
    const int p    = w * 4 + cg;         // col-pair 0..31 -> cols 2p,2p+1

    const float* xb = Xg + (size_t)b * (F_DIM * E_DIM);

    // ---- load X -> XS (scalar) and XST (transposed) ----
    for (int i = tid; i < F_DIM * E_DIM / 4; i += 256) {
        float4 v = reinterpret_cast<const float4*>(xb)[i];
        int f  = i >> 4;
        int e4 = (i & 15) * 4;
        *reinterpret_cast<float4*>(XS + f * XS_LD + e4) = v;
        XST[(e4 + 0) * XST_LD + f] = v.x;
        XST[(e4 + 1) * XST_LD + f] = v.y;
        XST[(e4 + 2) * XST_LD + f] = v.z;
        XST[(e4 + 3) * XST_LD + f] = v.w;
    }

    for (int h = 0; h < H_DIM; h++) {
        __syncthreads();   // protect weight buffers (+ XS/XST on first iter)

        // ---- stage WA=M_h, WB=Wv_h, WC=Wres[:, h*64:(h+1)*64] ----
        {
            const float4* msrc = reinterpret_cast<const float4*>(g_M + h * 4096);
            const float4* vsrc = reinterpret_cast<const float4*>(Wv + h * 4096);
            for (int i = tid; i < 1024; i += 256) {
                reinterpret_cast<float4*>(WA)[i] = msrc[i];
                reinterpret_cast<float4*>(WB)[i] = vsrc[i];
                int e  = i >> 4;
                int c4 = i & 15;
                reinterpret_cast<float4*>(WC + e * 64)[c4] =
                    *reinterpret_cast<const float4*>(Wres + e * 256 + h * 64 + 4 * c4);
            }
        }
        __syncthreads();

        // ---- GEMM1: t = X@M, v = X@Wv, r = X@WresBlk  (K=64, shared A) ----
        {
            ULL ts[5] = {}, vs[5] = {}, rs[5] = {};
            #pragma unroll 2
            for (int k4 = 0; k4 < 16; k4++) {
                float a[5][4];
                #pragma unroll
                for (int i = 0; i < 5; i++) {
                    float4 av = *reinterpret_cast<const float4*>(
                        XS + (rg + 8 * i) * XS_LD + 4 * k4);
                    a[i][0] = av.x; a[i][1] = av.y; a[i][2] = av.z; a[i][3] = av.w;
                }
                #pragma unroll
                for (int kk = 0; kk < 4; kk++) {
                    int k = 4 * k4 + kk;
                    ULL bA = *reinterpret_cast<const ULL*>(WA + k * 64 + 2 * p);
                    ULL bB = *reinterpret_cast<const ULL*>(WB + k * 64 + 2 * p);
                    ULL bC = *reinterpret_cast<const ULL*>(WC + k * 64 + 2 * p);
                    #pragma unroll
                    for (int i = 0; i < 5; i++) {
                        ULL ad = dup2(a[i][kk]);
                        fma2(ts[i], ad, bA);
                        fma2(vs[i], ad, bB);
                        fma2(rs[i], ad, bC);
                    }
                }
            }
            #pragma unroll
            for (int i = 0; i < 5; i++) {
                int r = rg + 8 * i;
                *reinterpret_cast<ULL*>(TS + r * TS_LD + 2 * p) = ts[i];
                *reinterpret_cast<ULL*>(VS + r * VS_LD + 2 * p) = vs[i];
                *reinterpret_cast<ULL*>(RS + r * RS_LD + 2 * p) = rs[i];
            }
        }
        __syncthreads();

        // ---- scores: PS[40,40] = TS @ XST  (warps 0-4) ----
        if (w < 5) {
            const int q = p;                 // 0..19 -> cols 2q,2q+1
            ULL ps[5] = {};
            #pragma unroll 2
            for (int k4 = 0; k4 < 16; k4++) {
                float a[5][4];
                #pragma unroll
                for (int i = 0; i < 5; i++) {
                    float4 av = *reinterpret_cast<const float4*>(
                        TS + (rg + 8 * i) * TS_LD + 4 * k4);
                    a[i][0] = av.x; a[i][1] = av.y; a[i][2] = av.z; a[i][3] = av.w;
                }
                #pragma unroll
                for (int kk = 0; kk < 4; kk++) {
                    int k = 4 * k4 + kk;
                    ULL bx = *reinterpret_cast<const ULL*>(XST + k * XST_LD + 2 * q);
                    #pragma unroll
                    for (int i = 0; i < 5; i++)
                        fma2(ps[i], dup2(a[i][kk]), bx);
                }
            }
            #pragma unroll
            for (int i = 0; i < 5; i++)
                *reinterpret_cast<ULL*>(PS + (rg + 8 * i) * PS_LD + 2 * q) = ps[i];
        }
        __syncthreads();

        // ---- softmax over rows of PS ----
        {
            #pragma unroll
            for (int j = 0; j < 5; j++) {
                int r = w + 8 * j;
                float v1 = PS[r * PS_LD + lane];
                float v2 = (lane < 8) ? PS[r * PS_LD + 32 + lane] : -3.4e38f;
                float m = fmaxf(v1, v2);
                #pragma unroll
                for (int o = 16; o; o >>= 1)
                    m = fmaxf(m, __shfl_xor_sync(0xffffffffu, m, o));
                float e1 = __expf(v1 - m);
                float e2 = (lane < 8) ? __expf(v2 - m) : 0.f;
                float s = e1 + e2;
                #pragma unroll
                for (int o = 16; o; o >>= 1)
                    s += __shfl_xor_sync(0xffffffffu, s, o);
                float inv = 1.f / s;
                PS[r * PS_LD + lane] = e1 * inv;
                if (lane < 8) PS[r * PS_LD + 32 + lane] = e2 * inv;
            }
        }
        __syncthreads();

        // ---- out = attn @ VS (K=40) + RS ; relu ; store ----
        {
            ULL acc[5] = {};
            #pragma unroll 2
            for (int k4 = 0; k4 < 10; k4++) {
                float a[5][4];
                #pragma unroll
                for (int i = 0; i < 5; i++) {
                    float4 av = *reinterpret_cast<const float4*>(
                        PS + (rg + 8 * i) * PS_LD + 4 * k4);
                    a[i][0] = av.x; a[i][1] = av.y; a[i][2] = av.z; a[i][3] = av.w;
                }
                #pragma unroll
                for (int kk = 0; kk < 4; kk++) {
                    int k = 4 * k4 + kk;
                    ULL bv = *reinterpret_cast<const ULL*>(VS + k * VS_LD + 2 * p);
                    #pragma unroll
                    for (int i = 0; i < 5; i++)
                        fma2(acc[i], dup2(a[i][kk]), bv);
                }
            }
            float* ob = out + (size_t)b * (F_DIM * 256) + h * 64 + 2 * p;
            #pragma unroll
            for (int i = 0; i < 5; i++) {
                int f = rg + 8 * i;
                ULL rsv = *reinterpret_cast<const ULL*>(RS + f * RS_LD + 2 * p);
                float2 r = unpack2(add2(acc[i], rsv));
                *reinterpret_cast<float2*>(ob + f * 256) =
                    make_float2(fmaxf(r.x, 0.f), fmaxf(r.y, 0.f));
            }
        }
    }
}

// ----------------------------------------------------------------------------
extern "C" void kernel_launch(void* const* d_in, const int* in_sizes, int n_in,
                              void* d_out, int out_size) {
    const float* X    = (const float*)d_in[0];
    const float* Wq   = (const float*)d_in[1];
    const float* Wk   = (const float*)d_in[2];
    const float* Wv   = (const float*)d_in[3];
    const float* Wres = (const float*)d_in[4];
    float* out = (float*)d_out;

    cudaFuncSetAttribute(attn_main_kernel,
                         cudaFuncAttributeMaxDynamicSharedMemorySize, SMEM_BYTES);

    precompute_M_kernel<<<H_DIM, 256>>>(Wq, Wk);
    attn_main_kernel<<<B_DIM, 256, SMEM_BYTES>>>(X, Wv, Wres, out);
}

// round 6
// speedup vs baseline: 1.3889x; 1.0017x over previous
#include <cuda_runtime.h>
#include <cuda_bf16.h>

// ============================================================================
// AutoInt MHA — fp32 FFMA2, round 5.
// Fix vs round 2-4 (L1TEX 92.8% bound): crossbar cost = bytes DELIVERED, so
//  * A matrices (X, T, attn) stored SCALAR; {a,a} pairs built with 1 MOV each
//    (ALU/issue had headroom) -> A smem traffic halved.
//  * Residual fused into GEMM1 as 3rd output sharing A loads; result parked
//    in RS, re-added in epilogue. GEMM3 is attn@V only.
// One CTA/batch, 256 thr, 2 CTA/SM. scores = X (Wq Wk^T) X^T, M precomputed.
// ============================================================================

#define B_DIM 4096
#define F_DIM 40
#define E_DIM 64
#define A_DIM 64
#define H_DIM 4

typedef unsigned long long ULL;

#define XS_LD  68
#define XST_LD 44
#define TS_LD  68
#define VS_LD  68
#define RS_LD  68
#define PS_LD  44

#define OFF_XS  0
#define OFF_XST (OFF_XS  + F_DIM * XS_LD)    // 2720
#define OFF_WA  (OFF_XST + E_DIM * XST_LD)   // 5536
#define OFF_WB  (OFF_WA  + 4096)             // 9632
#define OFF_WC  (OFF_WB  + 4096)             // 13728
#define OFF_TS  (OFF_WC  + 4096)             // 17824
#define OFF_VS  (OFF_TS  + F_DIM * TS_LD)    // 20544
#define OFF_RS  (OFF_VS  + F_DIM * VS_LD)    // 23264
#define OFF_PS  (OFF_RS  + F_DIM * RS_LD)    // 25984
#define SMEM_FLOATS (OFF_PS + F_DIM * PS_LD) // 27744
#define SMEM_BYTES  (SMEM_FLOATS * 4)        // 110976 -> 2 CTAs/SM

__device__ float g_M[H_DIM * E_DIM * E_DIM];

// ---- packed helpers --------------------------------------------------------
__device__ __forceinline__ void fma2(ULL& acc, ULL a, ULL b) {
    asm("fma.rn.f32x2 %0, %1, %2, %0;" : "+l"(acc) : "l"(a), "l"(b));
}
__device__ __forceinline__ ULL dup2(float f) {
    ULL r;
    asm("mov.b64 %0, {%1, %1};" : "=l"(r) : "f"(f));
    return r;
}
__device__ __forceinline__ float2 unpack2(ULL v) {
    float2 r;
    asm("mov.b64 {%0, %1}, %2;" : "=f"(r.x), "=f"(r.y) : "l"(v));
    return r;
}
__device__ __forceinline__ ULL add2(ULL a, ULL b) {
    ULL r;
    asm("add.rn.f32x2 %0, %1, %2;" : "=l"(r) : "l"(a), "l"(b));
    return r;
}

// ----------------------------------------------------------------------------
__global__ void precompute_M_kernel(const float* __restrict__ Wq,
                                    const float* __restrict__ Wk) {
    int h = blockIdx.x;
    __shared__ float sq[E_DIM * A_DIM];
    __shared__ float sk[E_DIM * A_DIM];
    const float* wq = Wq + h * E_DIM * A_DIM;
    const float* wk = Wk + h * E_DIM * A_DIM;
    for (int i = threadIdx.x; i < E_DIM * A_DIM; i += 256) {
        sq[i] = wq[i];
        sk[i] = wk[i];
    }
    __syncthreads();
    for (int idx = threadIdx.x; idx < E_DIM * E_DIM; idx += 256) {
        int e  = idx >> 6;
        int ep = idx & 63;
        float s = 0.f;
        #pragma unroll 8
        for (int a = 0; a < A_DIM; a++)
            s = fmaf(sq[e * A_DIM + a], sk[ep * A_DIM + a], s);
        g_M[h * E_DIM * E_DIM + idx] = s;
    }
}

// ----------------------------------------------------------------------------
__global__ void __launch_bounds__(256, 2)
attn_main_kernel(const float* __restrict__ Xg,
                 const float* __restrict__ Wv,
                 const float* __restrict__ Wres,
                 float* __restrict__ out) {
    extern __shared__ float sm[];
    float* XS  = sm + OFF_XS;
    float* XST = sm + OFF_XST;
    float* WA  = sm + OFF_WA;
    float* WB  = sm + OFF_WB;
    float* WC  = sm + OFF_WC;
    float* TS  = sm + OFF_TS;
    float* VS  = sm + OFF_VS;
    float* RS  = sm + OFF_RS;
    float* PS  = sm + OFF_PS;

    const int tid  = threadIdx.x;
    const int b    = blockIdx.x;
    const int w    = tid >> 5;
    const int lane = tid & 31;
    const int rg   = lane >> 2;          // rows rg, rg+8, ..., rg+32
    const int cg   = lane & 3;
    const int p    = w * 4 + cg;         // col-pair 0..31 -> cols 2p,2p+1

    const float* xb = Xg + (size_t)b * (F_DIM * E_DIM);

    // ---- load X -> XS (scalar) and XST (transposed) ----
    for (int i = tid; i < F_DIM * E_DIM / 4; i += 256) {
        float4 v = reinterpret_cast<const float4*>(xb)[i];
        int f  = i >> 4;
        int e4 = (i & 15) * 4;
        *reinterpret_cast<float4*>(XS + f * XS_LD + e4) = v;
        XST[(e4 + 0) * XST_LD + f] = v.x;
        XST[(e4 + 1) * XST_LD + f] = v.y;
        XST[(e4 + 2) * XST_LD + f] = v.z;
        XST[(e4 + 3) * XST_LD + f] = v.w;
    }

    for (int h = 0; h < H_DIM; h++) {
        __syncthreads();   // protect weight buffers (+ XS/XST on first iter)

        // ---- stage WA=M_h, WB=Wv_h, WC=Wres[:, h*64:(h+1)*64] ----
        {
            const float4* msrc = reinterpret_cast<const float4*>(g_M + h * 4096);
            const float4* vsrc = reinterpret_cast<const float4*>(Wv + h * 4096);
            for (int i = tid; i < 1024; i += 256) {
                reinterpret_cast<float4*>(WA)[i] = msrc[i];
                reinterpret_cast<float4*>(WB)[i] = vsrc[i];
                int e  = i >> 4;
                int c4 = i & 15;
                reinterpret_cast<float4*>(WC + e * 64)[c4] =
                    *reinterpret_cast<const float4*>(Wres + e * 256 + h * 64 + 4 * c4);
            }
        }
        __syncthreads();

        // ---- GEMM1: t = X@M, v = X@Wv, r = X@WresBlk  (K=64, shared A) ----
        {
            ULL ts[5] = {}, vs[5] = {}, rs[5] = {};
            #pragma unroll 2
            for (int k4 = 0; k4 < 16; k4++) {
                float a[5][4];
                #pragma unroll
                for (int i = 0; i < 5; i++) {
                    float4 av = *reinterpret_cast<const float4*>(
                        XS + (rg + 8 * i) * XS_LD + 4 * k4);
                    a[i][0] = av.x; a[i][1] = av.y; a[i][2] = av.z; a[i][3] = av.w;
                }
                #pragma unroll
                for (int kk = 0; kk < 4; kk++) {
                    int k = 4 * k4 + kk;
                    ULL bA = *reinterpret_cast<const ULL*>(WA + k * 64 + 2 * p);
                    ULL bB = *reinterpret_cast<const ULL*>(WB + k * 64 + 2 * p);
                    ULL bC = *reinterpret_cast<const ULL*>(WC + k * 64 + 2 * p);
                    #pragma unroll
                    for (int i = 0; i < 5; i++) {
                        ULL ad = dup2(a[i][kk]);
                        fma2(ts[i], ad, bA);
                        fma2(vs[i], ad, bB);
                        fma2(rs[i], ad, bC);
                    }
                }
            }
            #pragma unroll
            for (int i = 0; i < 5; i++) {
                int r = rg + 8 * i;
                *reinterpret_cast<ULL*>(TS + r * TS_LD + 2 * p) = ts[i];
                *reinterpret_cast<ULL*>(VS + r * VS_LD + 2 * p) = vs[i];
                *reinterpret_cast<ULL*>(RS + r * RS_LD + 2 * p) = rs[i];
            }
        }
        __syncthreads();

        // ---- scores: PS[40,40] = TS @ XST  (warps 0-4) ----
        if (w < 5) {
            const int q = p;                 // 0..19 -> cols 2q,2q+1
            ULL ps[5] = {};
            #pragma unroll 2
            for (int k4 = 0; k4 < 16; k4++) {
                float a[5][4];
                #pragma unroll
                for (int i = 0; i < 5; i++) {
                    float4 av = *reinterpret_cast<const float4*>(
                        TS + (rg + 8 * i) * TS_LD + 4 * k4);
                    a[i][0] = av.x; a[i][1] = av.y; a[i][2] = av.z; a[i][3] = av.w;
                }
                #pragma unroll
                for (int kk = 0; kk < 4; kk++) {
                    int k = 4 * k4 + kk;
                    ULL bx = *reinterpret_cast<const ULL*>(XST + k * XST_LD + 2 * q);
                    #pragma unroll
                    for (int i = 0; i < 5; i++)
                        fma2(ps[i], dup2(a[i][kk]), bx);
                }
            }
            #pragma unroll
            for (int i = 0; i < 5; i++)
                *reinterpret_cast<ULL*>(PS + (rg + 8 * i) * PS_LD + 2 * q) = ps[i];
        }
        __syncthreads();

        // ---- softmax over rows of PS ----
        {
            #pragma unroll
            for (int j = 0; j < 5; j++) {
                int r = w + 8 * j;
                float v1 = PS[r * PS_LD + lane];
                float v2 = (lane < 8) ? PS[r * PS_LD + 32 + lane] : -3.4e38f;
                float m = fmaxf(v1, v2);
                #pragma unroll
                for (int o = 16; o; o >>= 1)
                    m = fmaxf(m, __shfl_xor_sync(0xffffffffu, m, o));
                float e1 = __expf(v1 - m);
                float e2 = (lane < 8) ? __expf(v2 - m) : 0.f;
                float s = e1 + e2;
                #pragma unroll
                for (int o = 16; o; o >>= 1)
                    s += __shfl_xor_sync(0xffffffffu, s, o);
                float inv = 1.f / s;
                PS[r * PS_LD + lane] = e1 * inv;
                if (lane < 8) PS[r * PS_LD + 32 + lane] = e2 * inv;
            }
        }
        __syncthreads();

        // ---- out = attn @ VS (K=40) + RS ; relu ; store ----
        {
            ULL acc[5] = {};
            #pragma unroll 2
            for (int k4 = 0; k4 < 10; k4++) {
                float a[5][4];
                #pragma unroll
                for (int i = 0; i < 5; i++) {
                    float4 av = *reinterpret_cast<const float4*>(
                        PS + (rg + 8 * i) * PS_LD + 4 * k4);
                    a[i][0] = av.x; a[i][1] = av.y; a[i][2] = av.z; a[i][3] = av.w;
                }
                #pragma unroll
                for (int kk = 0; kk < 4; kk++) {
                    int k = 4 * k4 + kk;
                    ULL bv = *reinterpret_cast<const ULL*>(VS + k * VS_LD + 2 * p);
                    #pragma unroll
                    for (int i = 0; i < 5; i++)
                        fma2(acc[i], dup2(a[i][kk]), bv);
                }
            }
            float* ob = out + (size_t)b * (F_DIM * 256) + h * 64 + 2 * p;
            #pragma unroll
            for (int i = 0; i < 5; i++) {
                int f = rg + 8 * i;
                ULL rsv = *reinterpret_cast<const ULL*>(RS + f * RS_LD + 2 * p);
                float2 r = unpack2(add2(acc[i], rsv));
                *reinterpret_cast<float2*>(ob + f * 256) =
                    make_float2(fmaxf(r.x, 0.f), fmaxf(r.y, 0.f));
            }
        }
    }
}

// ----------------------------------------------------------------------------
extern "C" void kernel_launch(void* const* d_in, const int* in_sizes, int n_in,
                              void* d_out, int out_size) {
    const float* X    = (const float*)d_in[0];
    const float* Wq   = (const float*)d_in[1];
    const float* Wk   = (const float*)d_in[2];
    const float* Wv   = (const float*)d_in[3];
    const float* Wres = (const float*)d_in[4];
    float* out = (float*)d_out;

    cudaFuncSetAttribute(attn_main_kernel,
                         cudaFuncAttributeMaxDynamicSharedMemorySize, SMEM_BYTES);

    precompute_M_kernel<<<H_DIM, 256>>>(Wq, Wk);
    attn_main_kernel<<<B_DIM, 256, SMEM_BYTES>>>(X, Wv, Wres, out);
}

// round 7
// speedup vs baseline: 1.8397x; 1.3246x over previous
#include <cuda_runtime.h>
#include <cuda_bf16.h>
#include <cstdint>

// ============================================================================
// AutoInt MHA — round 7: split-bf16 tensor cores (mma.sync.m16n8k16).
// fp32 accuracy via 2-way split: A*B ~= Ah*Bh + Al*Bh + Ah*Bl (err ~1e-5).
// One CTA/batch (B=4096), 256 thr, 2 CTA/SM. scores = X (Wq Wk^T) X^T.
// Weights pre-split to bf16 hi/lo once (precompute kernel); staged per head
// with XOR swizzle for conflict-free ldmatrix.trans. F=40 padded to 48;
// all K-pads are exactly zero by construction.
// ============================================================================

#define B_DIM 4096
#define F_DIM 40
#define E_DIM 64
#define H_DIM 4

// ---- smem byte offsets ----
#define XH_OFF   0            // [48][72] bf16
#define XL_OFF   6912
#define XTH_OFF  13824        // [64][56] bf16 (X^T)
#define XTL_OFF  20992
#define W_OFF    28160        // 6 x 8192B: XOR-swizzled [64][64] bf16 (Mh,Ml,Vh,Vl,Rh,Rl)
#define PS_OFF   28160        // fp32 [40][52] scores — ALIASES W (written after GEMM1)
#define TH_OFF   77312        // [48][72] bf16 — aliased by PH [48][56] after softmax
#define TL_OFF   84224        // — aliased by PL
#define VH_OFF   91136        // [48][72] bf16
#define VL_OFF   98048
#define RS_OFF   104960       // fp32 [40][66] residual
#define SMEM_BYTES 115520

#define XA_LD 72   // XH/XL, TH/TL, VH/VL row stride (bf16 elems)
#define XT_LD 56   // XTH/XTL, PH/PL
#define PS_LD 52
#define RS_LD 66

__device__ __align__(16) __nv_bfloat16 g_W[H_DIM * 6 * 4096];

// ---- PTX helpers -----------------------------------------------------------
__device__ __forceinline__ uint32_t cvta_smem(const void* p) {
    uint32_t a;
    asm("{ .reg .u64 t; cvta.to.shared.u64 t, %1; cvt.u32.u64 %0, t; }"
        : "=r"(a) : "l"(p));
    return a;
}
__device__ __forceinline__ void ldsm4(uint32_t a, uint32_t r[4]) {
    asm volatile("ldmatrix.sync.aligned.m8n8.x4.shared.b16 {%0,%1,%2,%3}, [%4];"
        : "=r"(r[0]), "=r"(r[1]), "=r"(r[2]), "=r"(r[3]) : "r"(a));
}
__device__ __forceinline__ void ldsm2t(uint32_t a, uint32_t r[2]) {
    asm volatile("ldmatrix.sync.aligned.m8n8.x2.trans.shared.b16 {%0,%1}, [%2];"
        : "=r"(r[0]), "=r"(r[1]) : "r"(a));
}
__device__ __forceinline__ void mma16816(float c[4], const uint32_t a[4],
                                         const uint32_t b[2]) {
    asm volatile(
        "mma.sync.aligned.m16n8k16.row.col.f32.bf16.bf16.f32 "
        "{%0,%1,%2,%3}, {%4,%5,%6,%7}, {%8,%9}, {%0,%1,%2,%3};"
        : "+f"(c[0]), "+f"(c[1]), "+f"(c[2]), "+f"(c[3])
        : "r"(a[0]), "r"(a[1]), "r"(a[2]), "r"(a[3]), "r"(b[0]), "r"(b[1]));
}
__device__ __forceinline__ void split1(float x, __nv_bfloat16& h, __nv_bfloat16& l) {
    h = __float2bfloat16(x);
    l = __float2bfloat16(x - __bfloat162float(h));
}
__device__ __forceinline__ uint32_t packbf(__nv_bfloat16 a, __nv_bfloat16 b) {
    return (uint32_t)__bfloat16_as_ushort(a) |
           ((uint32_t)__bfloat16_as_ushort(b) << 16);
}

// ----------------------------------------------------------------------------
// Precompute: M_h = Wq_h @ Wk_h^T; split M, Wv, Wres-slice to bf16 hi/lo.
// grid = H, block = 256.
// ----------------------------------------------------------------------------
__global__ void precompute_kernel(const float* __restrict__ Wq,
                                  const float* __restrict__ Wk,
                                  const float* __restrict__ Wv,
                                  const float* __restrict__ Wres) {
    int h = blockIdx.x;
    __shared__ float sq[4096], sk[4096];
    for (int i = threadIdx.x; i < 4096; i += 256) {
        sq[i] = Wq[h * 4096 + i];
        sk[i] = Wk[h * 4096 + i];
    }
    __syncthreads();
    __nv_bfloat16* gw = g_W + h * 6 * 4096;
    for (int idx = threadIdx.x; idx < 4096; idx += 256) {
        int e = idx >> 6, ep = idx & 63;
        float s = 0.f;
        #pragma unroll 8
        for (int a = 0; a < 64; a++)
            s = fmaf(sq[e * 64 + a], sk[ep * 64 + a], s);
        __nv_bfloat16 hi, lo;
        split1(s, hi, lo);
        gw[0 * 4096 + idx] = hi; gw[1 * 4096 + idx] = lo;
        split1(Wv[h * 4096 + idx], hi, lo);
        gw[2 * 4096 + idx] = hi; gw[3 * 4096 + idx] = lo;
        split1(Wres[e * 256 + h * 64 + ep], hi, lo);
        gw[4 * 4096 + idx] = hi; gw[5 * 4096 + idx] = lo;
    }
}

// ----------------------------------------------------------------------------
__global__ void __launch_bounds__(256, 2)
attn_main_kernel(const float* __restrict__ Xg, float* __restrict__ out) {
    extern __shared__ char sm[];
    const uint32_t sb = cvta_smem(sm);
    float* PSf = (float*)(sm + PS_OFF);
    float* RSf = (float*)(sm + RS_OFF);

    const int tid  = threadIdx.x;
    const int b    = blockIdx.x;
    const int w    = tid >> 5;
    const int lane = tid & 31;
    const int lr   = lane & 15;
    const int lq   = lane >> 4;
    const int row4 = lane >> 2;
    const int col2 = 2 * (lane & 3);

    // ---- zero X buffers (pads must be exactly 0) ----
    for (int i = tid; i < 28160 / 16; i += 256)
        reinterpret_cast<uint4*>(sm)[i] = make_uint4(0, 0, 0, 0);
    __syncthreads();

    // ---- stage X: split to XH/XL and transposed XTH/XTL ----
    {
        const float4* xb = reinterpret_cast<const float4*>(Xg + (size_t)b * 2560);
        __nv_bfloat16* XH  = (__nv_bfloat16*)(sm + XH_OFF);
        __nv_bfloat16* XL  = (__nv_bfloat16*)(sm + XL_OFF);
        __nv_bfloat16* XTH = (__nv_bfloat16*)(sm + XTH_OFF);
        __nv_bfloat16* XTL = (__nv_bfloat16*)(sm + XTL_OFF);
        for (int i = tid; i < 640; i += 256) {
            float4 v = xb[i];
            int f = i >> 4, e0 = (i & 15) * 4;
            float vv[4] = {v.x, v.y, v.z, v.w};
            #pragma unroll
            for (int j = 0; j < 4; j++) {
                __nv_bfloat16 hi, lo;
                split1(vv[j], hi, lo);
                int e = e0 + j;
                XH[f * XA_LD + e] = hi;  XL[f * XA_LD + e] = lo;
                XTH[e * XT_LD + f] = hi; XTL[e * XT_LD + f] = lo;
            }
        }
    }

    for (int h = 0; h < H_DIM; h++) {
        __syncthreads();
        // ---- stage weights (XOR swizzle, 16B chunks) ----
        {
            const uint4* gw = reinterpret_cast<const uint4*>(g_W) + h * 6 * 512;
            for (int i = tid; i < 3072; i += 256) {
                int ms = i >> 9, r = (i >> 3) & 63, c = i & 7;
                *reinterpret_cast<uint4*>(sm + W_OFF + ms * 8192 + r * 128 +
                                          ((c ^ (r & 7)) << 4)) = gw[i];
            }
        }
        __syncthreads();

        // ==== GEMM1: t = X@M, v = X@Wv, r = X@Wres_h  (warp: 3 n-tiles) ====
        {
            float acc[3][3][4];
            #pragma unroll
            for (int j = 0; j < 3; j++)
                #pragma unroll
                for (int mt = 0; mt < 3; mt++)
                    #pragma unroll
                    for (int q = 0; q < 4; q++) acc[j][mt][q] = 0.f;

            #pragma unroll
            for (int kt = 0; kt < 4; kt++) {
                uint32_t ah[3][4], al[3][4];
                #pragma unroll
                for (int mt = 0; mt < 3; mt++) {
                    uint32_t a0 = sb + XH_OFF +
                        ((mt * 16 + lr) * XA_LD + kt * 16) * 2 + (lq << 4);
                    ldsm4(a0, ah[mt]);
                    ldsm4(a0 + (XL_OFF - XH_OFF), al[mt]);
                }
                #pragma unroll
                for (int j = 0; j < 3; j++) {
                    int nt = 3 * w + j;
                    int mat = nt >> 3, nc = (nt & 7) * 8;
                    int krow = kt * 16 + lr;
                    uint32_t bb = sb + W_OFF + (mat * 2) * 8192 + krow * 128 +
                                  (((nc >> 3) ^ (krow & 7)) << 4);
                    uint32_t bh[2], bl[2];
                    ldsm2t(bb, bh);
                    ldsm2t(bb + 8192, bl);
                    #pragma unroll
                    for (int mt = 0; mt < 3; mt++) {
                        mma16816(acc[j][mt], ah[mt], bh);
                        mma16816(acc[j][mt], al[mt], bh);
                        mma16816(acc[j][mt], ah[mt], bl);
                    }
                }
            }
            // epilogue
            #pragma unroll
            for (int j = 0; j < 3; j++) {
                int nt = 3 * w + j;
                int mat = nt >> 3, nc = (nt & 7) * 8;
                int c = nc + col2;
                #pragma unroll
                for (int mt = 0; mt < 3; mt++) {
                    int r0 = mt * 16 + row4, r1 = r0 + 8;
                    if (mat < 2) {
                        int base = (mat == 0) ? TH_OFF : VH_OFF;
                        __nv_bfloat16 h0, l0, h1, l1;
                        split1(acc[j][mt][0], h0, l0);
                        split1(acc[j][mt][1], h1, l1);
                        *reinterpret_cast<uint32_t*>(sm + base + (r0 * XA_LD + c) * 2) = packbf(h0, h1);
                        *reinterpret_cast<uint32_t*>(sm + base + 6912 + (r0 * XA_LD + c) * 2) = packbf(l0, l1);
                        split1(acc[j][mt][2], h0, l0);
                        split1(acc[j][mt][3], h1, l1);
                        *reinterpret_cast<uint32_t*>(sm + base + (r1 * XA_LD + c) * 2) = packbf(h0, h1);
                        *reinterpret_cast<uint32_t*>(sm + base + 6912 + (r1 * XA_LD + c) * 2) = packbf(l0, l1);
                    } else {
                        *reinterpret_cast<float2*>(RSf + r0 * RS_LD + c) =
                            make_float2(acc[j][mt][0], acc[j][mt][1]);
                        if (r1 < F_DIM)
                            *reinterpret_cast<float2*>(RSf + r1 * RS_LD + c) =
                                make_float2(acc[j][mt][2], acc[j][mt][3]);
                    }
                }
            }
        }
        __syncthreads();

        // ==== scores: PS = T @ X^T  (warps 0-5, n-tile = w) ====
        if (w < 6) {
            int nc = w * 8;
            float sacc[3][4];
            #pragma unroll
            for (int mt = 0; mt < 3; mt++)
                #pragma unroll
                for (int q = 0; q < 4; q++) sacc[mt][q] = 0.f;
            #pragma unroll
            for (int kt = 0; kt < 4; kt++) {
                uint32_t ah[3][4], al[3][4];
                #pragma unroll
                for (int mt = 0; mt < 3; mt++) {
                    uint32_t a0 = sb + TH_OFF +
                        ((mt * 16 + lr) * XA_LD + kt * 16) * 2 + (lq << 4);
                    ldsm4(a0, ah[mt]);
                    ldsm4(a0 + 6912, al[mt]);
                }
                uint32_t bb = sb + XTH_OFF + ((kt * 16 + lr) * XT_LD + nc) * 2;
                uint32_t bh[2], bl[2];
                ldsm2t(bb, bh);
                ldsm2t(bb + (XTL_OFF - XTH_OFF), bl);
                #pragma unroll
                for (int mt = 0; mt < 3; mt++) {
                    mma16816(sacc[mt], ah[mt], bh);
                    mma16816(sacc[mt], al[mt], bh);
                    mma16816(sacc[mt], ah[mt], bl);
                }
            }
            int c = nc + col2;
            #pragma unroll
            for (int mt = 0; mt < 3; mt++) {
                int r0 = mt * 16 + row4, r1 = r0 + 8;
                *reinterpret_cast<float2*>(PSf + r0 * PS_LD + c) =
                    make_float2(sacc[mt][0], sacc[mt][1]);
                if (r1 < F_DIM)
                    *reinterpret_cast<float2*>(PSf + r1 * PS_LD + c) =
                        make_float2(sacc[mt][2], sacc[mt][3]);
            }
        }
        __syncthreads();

        // ==== softmax -> PH/PL (aliased over TH/TL), zero k-pad cols ====
        {
            __nv_bfloat16* PH = (__nv_bfloat16*)(sm + TH_OFF);
            __nv_bfloat16* PL = (__nv_bfloat16*)(sm + TL_OFF);
            #pragma unroll
            for (int j = 0; j < 5; j++) {
                int r = w + 8 * j;
                float v1 = PSf[r * PS_LD + lane];
                float v2 = (lane < 8) ? PSf[r * PS_LD + 32 + lane] : -3.4e38f;
                float m = fmaxf(v1, v2);
                #pragma unroll
                for (int o = 16; o; o >>= 1)
                    m = fmaxf(m, __shfl_xor_sync(0xffffffffu, m, o));
                float e1 = __expf(v1 - m);
                float e2 = (lane < 8) ? __expf(v2 - m) : 0.f;
                float s = e1 + e2;
                #pragma unroll
                for (int o = 16; o; o >>= 1)
                    s += __shfl_xor_sync(0xffffffffu, s, o);
                float inv = 1.f / s;
                __nv_bfloat16 ph, pl;
                split1(e1 * inv, ph, pl);
                PH[r * XT_LD + lane] = ph;
                PL[r * XT_LD + lane] = pl;
                if (lane < 8) {
                    split1(e2 * inv, ph, pl);
                    PH[r * XT_LD + 32 + lane] = ph;
                    PL[r * XT_LD + 32 + lane] = pl;
                    PH[r * XT_LD + 40 + lane] = __ushort_as_bfloat16(0);
                    PL[r * XT_LD + 40 + lane] = __ushort_as_bfloat16(0);
                }
            }
        }
        __syncthreads();

        // ==== GEMM3: out = attn @ V + RS ; relu ; store (n-tile = w) ====
        {
            int nc = w * 8;
            float oacc[3][4];
            #pragma unroll
            for (int mt = 0; mt < 3; mt++)
                #pragma unroll
                for (int q = 0; q < 4; q++) oacc[mt][q] = 0.f;
            #pragma unroll
            for (int kt = 0; kt < 3; kt++) {
                uint32_t ah[3][4], al[3][4];
                #pragma unroll
                for (int mt = 0; mt < 3; mt++) {
                    uint32_t a0 = sb + TH_OFF +
                        ((mt * 16 + lr) * XT_LD + kt * 16) * 2 + (lq << 4);
                    ldsm4(a0, ah[mt]);
                    ldsm4(a0 + 6912, al[mt]);
                }
                uint32_t bb = sb + VH_OFF + ((kt * 16 + lr) * XA_LD + nc) * 2;
                uint32_t bh[2], bl[2];
                ldsm2t(bb, bh);
                ldsm2t(bb + 6912, bl);
                #pragma unroll
                for (int mt = 0; mt < 3; mt++) {
                    mma16816(oacc[mt], ah[mt], bh);
                    mma16816(oacc[mt], al[mt], bh);
                    mma16816(oacc[mt], ah[mt], bl);
                }
            }
            int c = nc + col2;
            float* ob = out + (size_t)b * (F_DIM * 256) + h * 64 + c;
            #pragma unroll
            for (int mt = 0; mt < 3; mt++) {
                int f0 = mt * 16 + row4, f1 = f0 + 8;
                float2 rs0 = *reinterpret_cast<const float2*>(RSf + f0 * RS_LD + c);
                *reinterpret_cast<float2*>(ob + f0 * 256) =
                    make_float2(fmaxf(oacc[mt][0] + rs0.x, 0.f),
                                fmaxf(oacc[mt][1] + rs0.y, 0.f));
                if (f1 < F_DIM) {
                    float2 rs1 = *reinterpret_cast<const float2*>(RSf + f1 * RS_LD + c);
                    *reinterpret_cast<float2*>(ob + f1 * 256) =
                        make_float2(fmaxf(oacc[mt][2] + rs1.x, 0.f),
                                    fmaxf(oacc[mt][3] + rs1.y, 0.f));
                }
            }
        }
    }
}

// ----------------------------------------------------------------------------
extern "C" void kernel_launch(void* const* d_in, const int* in_sizes, int n_in,
                              void* d_out, int out_size) {
    const float* X    = (const float*)d_in[0];
    const float* Wq   = (const float*)d_in[1];
    const float* Wk   = (const float*)d_in[2];
    const float* Wv   = (const float*)d_in[3];
    const float* Wres = (const float*)d_in[4];
    float* out = (float*)d_out;

    cudaFuncSetAttribute(attn_main_kernel,
                         cudaFuncAttributeMaxDynamicSharedMemorySize, SMEM_BYTES);

    precompute_kernel<<<H_DIM, 256>>>(Wq, Wk, Wv, Wres);
    attn_main_kernel<<<B_DIM, 256, SMEM_BYTES>>>(X, out);
}

// round 8
// speedup vs baseline: 1.8442x; 1.0025x over previous
#include <cuda_runtime.h>
#include <cuda_bf16.h>
#include <cstdint>

// ============================================================================
// AutoInt MHA — round 7: split-bf16 tensor cores (mma.sync.m16n8k16).
// fp32 accuracy via 2-way split: A*B ~= Ah*Bh + Al*Bh + Ah*Bl (err ~1e-5).
// One CTA/batch (B=4096), 256 thr, 2 CTA/SM. scores = X (Wq Wk^T) X^T.
// Weights pre-split to bf16 hi/lo once (precompute kernel); staged per head
// with XOR swizzle for conflict-free ldmatrix.trans. F=40 padded to 48;
// all K-pads are exactly zero by construction.
// ============================================================================

#define B_DIM 4096
#define F_DIM 40
#define E_DIM 64
#define H_DIM 4

// ---- smem byte offsets ----
#define XH_OFF   0            // [48][72] bf16
#define XL_OFF   6912
#define XTH_OFF  13824        // [64][56] bf16 (X^T)
#define XTL_OFF  20992
#define W_OFF    28160        // 6 x 8192B: XOR-swizzled [64][64] bf16 (Mh,Ml,Vh,Vl,Rh,Rl)
#define PS_OFF   28160        // fp32 [40][52] scores — ALIASES W (written after GEMM1)
#define TH_OFF   77312        // [48][72] bf16 — aliased by PH [48][56] after softmax
#define TL_OFF   84224        // — aliased by PL
#define VH_OFF   91136        // [48][72] bf16
#define VL_OFF   98048
#define RS_OFF   104960       // fp32 [40][66] residual
#define SMEM_BYTES 115520

#define XA_LD 72   // XH/XL, TH/TL, VH/VL row stride (bf16 elems)
#define XT_LD 56   // XTH/XTL, PH/PL
#define PS_LD 52
#define RS_LD 66

__device__ __align__(16) __nv_bfloat16 g_W[H_DIM * 6 * 4096];

// ---- PTX helpers -----------------------------------------------------------
__device__ __forceinline__ uint32_t cvta_smem(const void* p) {
    uint32_t a;
    asm("{ .reg .u64 t; cvta.to.shared.u64 t, %1; cvt.u32.u64 %0, t; }"
        : "=r"(a) : "l"(p));
    return a;
}
__device__ __forceinline__ void ldsm4(uint32_t a, uint32_t r[4]) {
    asm volatile("ldmatrix.sync.aligned.m8n8.x4.shared.b16 {%0,%1,%2,%3}, [%4];"
        : "=r"(r[0]), "=r"(r[1]), "=r"(r[2]), "=r"(r[3]) : "r"(a));
}
__device__ __forceinline__ void ldsm2t(uint32_t a, uint32_t r[2]) {
    asm volatile("ldmatrix.sync.aligned.m8n8.x2.trans.shared.b16 {%0,%1}, [%2];"
        : "=r"(r[0]), "=r"(r[1]) : "r"(a));
}
__device__ __forceinline__ void mma16816(float c[4], const uint32_t a[4],
                                         const uint32_t b[2]) {
    asm volatile(
        "mma.sync.aligned.m16n8k16.row.col.f32.bf16.bf16.f32 "
        "{%0,%1,%2,%3}, {%4,%5,%6,%7}, {%8,%9}, {%0,%1,%2,%3};"
        : "+f"(c[0]), "+f"(c[1]), "+f"(c[2]), "+f"(c[3])
        : "r"(a[0]), "r"(a[1]), "r"(a[2]), "r"(a[3]), "r"(b[0]), "r"(b[1]));
}
__device__ __forceinline__ void split1(float x, __nv_bfloat16& h, __nv_bfloat16& l) {
    h = __float2bfloat16(x);
    l = __float2bfloat16(x - __bfloat162float(h));
}
__device__ __forceinline__ uint32_t packbf(__nv_bfloat16 a, __nv_bfloat16 b) {
    return (uint32_t)__bfloat16_as_ushort(a) |
           ((uint32_t)__bfloat16_as_ushort(b) << 16);
}

// ----------------------------------------------------------------------------
// Precompute: M_h = Wq_h @ Wk_h^T; split M, Wv, Wres-slice to bf16 hi/lo.
// grid = H, block = 256.
// ----------------------------------------------------------------------------
__global__ void precompute_kernel(const float* __restrict__ Wq,
                                  const float* __restrict__ Wk,
                                  const float* __restrict__ Wv,
                                  const float* __restrict__ Wres) {
    int h = blockIdx.x;
    __shared__ float sq[4096], sk[4096];
    for (int i = threadIdx.x; i < 4096; i += 256) {
        sq[i] = Wq[h * 4096 + i];
        sk[i] = Wk[h * 4096 + i];
    }
    __syncthreads();
    __nv_bfloat16* gw = g_W + h * 6 * 4096;
    for (int idx = threadIdx.x; idx < 4096; idx += 256) {
        int e = idx >> 6, ep = idx & 63;
        float s = 0.f;
        #pragma unroll 8
        for (int a = 0; a < 64; a++)
            s = fmaf(sq[e * 64 + a], sk[ep * 64 + a], s);
        __nv_bfloat16 hi, lo;
        split1(s, hi, lo);
        gw[0 * 4096 + idx] = hi; gw[1 * 4096 + idx] = lo;
        split1(Wv[h * 4096 + idx], hi, lo);
        gw[2 * 4096 + idx] = hi; gw[3 * 4096 + idx] = lo;
        split1(Wres[e * 256 + h * 64 + ep], hi, lo);
        gw[4 * 4096 + idx] = hi; gw[5 * 4096 + idx] = lo;
    }
}

// ----------------------------------------------------------------------------
__global__ void __launch_bounds__(256, 2)
attn_main_kernel(const float* __restrict__ Xg, float* __restrict__ out) {
    extern __shared__ char sm[];
    const uint32_t sb = cvta_smem(sm);
    float* PSf = (float*)(sm + PS_OFF);
    float* RSf = (float*)(sm + RS_OFF);

    const int tid  = threadIdx.x;
    const int b    = blockIdx.x;
    const int w    = tid >> 5;
    const int lane = tid & 31;
    const int lr   = lane & 15;
    const int lq   = lane >> 4;
    const int row4 = lane >> 2;
    const int col2 = 2 * (lane & 3);

    // ---- zero X buffers (pads must be exactly 0) ----
    for (int i = tid; i < 28160 / 16; i += 256)
        reinterpret_cast<uint4*>(sm)[i] = make_uint4(0, 0, 0, 0);
    __syncthreads();

    // ---- stage X: split to XH/XL and transposed XTH/XTL ----
    {
        const float4* xb = reinterpret_cast<const float4*>(Xg + (size_t)b * 2560);
        __nv_bfloat16* XH  = (__nv_bfloat16*)(sm + XH_OFF);
        __nv_bfloat16* XL  = (__nv_bfloat16*)(sm + XL_OFF);
        __nv_bfloat16* XTH = (__nv_bfloat16*)(sm + XTH_OFF);
        __nv_bfloat16* XTL = (__nv_bfloat16*)(sm + XTL_OFF);
        for (int i = tid; i < 640; i += 256) {
            float4 v = xb[i];
            int f = i >> 4, e0 = (i & 15) * 4;
            float vv[4] = {v.x, v.y, v.z, v.w};
            #pragma unroll
            for (int j = 0; j < 4; j++) {
                __nv_bfloat16 hi, lo;
                split1(vv[j], hi, lo);
                int e = e0 + j;
                XH[f * XA_LD + e] = hi;  XL[f * XA_LD + e] = lo;
                XTH[e * XT_LD + f] = hi; XTL[e * XT_LD + f] = lo;
            }
        }
    }

    for (int h = 0; h < H_DIM; h++) {
        __syncthreads();
        // ---- stage weights (XOR swizzle, 16B chunks) ----
        {
            const uint4* gw = reinterpret_cast<const uint4*>(g_W) + h * 6 * 512;
            for (int i = tid; i < 3072; i += 256) {
                int ms = i >> 9, r = (i >> 3) & 63, c = i & 7;
                *reinterpret_cast<uint4*>(sm + W_OFF + ms * 8192 + r * 128 +
                                          ((c ^ (r & 7)) << 4)) = gw[i];
            }
        }
        __syncthreads();

        // ==== GEMM1: t = X@M, v = X@Wv, r = X@Wres_h  (warp: 3 n-tiles) ====
        {
            float acc[3][3][4];
            #pragma unroll
            for (int j = 0; j < 3; j++)
                #pragma unroll
                for (int mt = 0; mt < 3; mt++)
                    #pragma unroll
                    for (int q = 0; q < 4; q++) acc[j][mt][q] = 0.f;

            #pragma unroll
            for (int kt = 0; kt < 4; kt++) {
                uint32_t ah[3][4], al[3][4];
                #pragma unroll
                for (int mt = 0; mt < 3; mt++) {
                    uint32_t a0 = sb + XH_OFF +
                        ((mt * 16 + lr) * XA_LD + kt * 16) * 2 + (lq << 4);
                    ldsm4(a0, ah[mt]);
                    ldsm4(a0 + (XL_OFF - XH_OFF), al[mt]);
                }
                #pragma unroll
                for (int j = 0; j < 3; j++) {
                    int nt = 3 * w + j;
                    int mat = nt >> 3, nc = (nt & 7) * 8;
                    int krow = kt * 16 + lr;
                    uint32_t bb = sb + W_OFF + (mat * 2) * 8192 + krow * 128 +
                                  (((nc >> 3) ^ (krow & 7)) << 4);
                    uint32_t bh[2], bl[2];
                    ldsm2t(bb, bh);
                    ldsm2t(bb + 8192, bl);
                    #pragma unroll
                    for (int mt = 0; mt < 3; mt++) {
                        mma16816(acc[j][mt], ah[mt], bh);
                        mma16816(acc[j][mt], al[mt], bh);
                        mma16816(acc[j][mt], ah[mt], bl);
                    }
                }
            }
            // epilogue
            #pragma unroll
            for (int j = 0; j < 3; j++) {
                int nt = 3 * w + j;
                int mat = nt >> 3, nc = (nt & 7) * 8;
                int c = nc + col2;
                #pragma unroll
                for (int mt = 0; mt < 3; mt++) {
                    int r0 = mt * 16 + row4, r1 = r0 + 8;
                    if (mat < 2) {
                        int base = (mat == 0) ? TH_OFF : VH_OFF;
                        __nv_bfloat16 h0, l0, h1, l1;
                        split1(acc[j][mt][0], h0, l0);
                        split1(acc[j][mt][1], h1, l1);
                        *reinterpret_cast<uint32_t*>(sm + base + (r0 * XA_LD + c) * 2) = packbf(h0, h1);
                        *reinterpret_cast<uint32_t*>(sm + base + 6912 + (r0 * XA_LD + c) * 2) = packbf(l0, l1);
                        split1(acc[j][mt][2], h0, l0);
                        split1(acc[j][mt][3], h1, l1);
                        *reinterpret_cast<uint32_t*>(sm + base + (r1 * XA_LD + c) * 2) = packbf(h0, h1);
                        *reinterpret_cast<uint32_t*>(sm + base + 6912 + (r1 * XA_LD + c) * 2) = packbf(l0, l1);
                    } else {
                        *reinterpret_cast<float2*>(RSf + r0 * RS_LD + c) =
                            make_float2(acc[j][mt][0], acc[j][mt][1]);
                        if (r1 < F_DIM)
                            *reinterpret_cast<float2*>(RSf + r1 * RS_LD + c) =
                                make_float2(acc[j][mt][2], acc[j][mt][3]);
                    }
                }
            }
        }
        __syncthreads();

        // ==== scores: PS = T @ X^T  (warps 0-5, n-tile = w) ====
        if (w < 6) {
            int nc = w * 8;
            float sacc[3][4];
            #pragma unroll
            for (int mt = 0; mt < 3; mt++)
                #pragma unroll
                for (int q = 0; q < 4; q++) sacc[mt][q] = 0.f;
            #pragma unroll
            for (int kt = 0; kt < 4; kt++) {
                uint32_t ah[3][4], al[3][4];
                #pragma unroll
                for (int mt = 0; mt < 3; mt++) {
                    uint32_t a0 = sb + TH_OFF +
                        ((mt * 16 + lr) * XA_LD + kt * 16) * 2 + (lq << 4);
                    ldsm4(a0, ah[mt]);
                    ldsm4(a0 + 6912, al[mt]);
                }
                uint32_t bb = sb + XTH_OFF + ((kt * 16 + lr) * XT_LD + nc) * 2;
                uint32_t bh[2], bl[2];
                ldsm2t(bb, bh);
                ldsm2t(bb + (XTL_OFF - XTH_OFF), bl);
                #pragma unroll
                for (int mt = 0; mt < 3; mt++) {
                    mma16816(sacc[mt], ah[mt], bh);
                    mma16816(sacc[mt], al[mt], bh);
                    mma16816(sacc[mt], ah[mt], bl);
                }
            }
            int c = nc + col2;
            #pragma unroll
            for (int mt = 0; mt < 3; mt++) {
                int r0 = mt * 16 + row4, r1 = r0 + 8;
                *reinterpret_cast<float2*>(PSf + r0 * PS_LD + c) =
                    make_float2(sacc[mt][0], sacc[mt][1]);
                if (r1 < F_DIM)
                    *reinterpret_cast<float2*>(PSf + r1 * PS_LD + c) =
                        make_float2(sacc[mt][2], sacc[mt][3]);
            }
        }
        __syncthreads();

        // ==== softmax -> PH/PL (aliased over TH/TL), zero k-pad cols ====
        {
            __nv_bfloat16* PH = (__nv_bfloat16*)(sm + TH_OFF);
            __nv_bfloat16* PL = (__nv_bfloat16*)(sm + TL_OFF);
            #pragma unroll
            for (int j = 0; j < 5; j++) {
                int r = w + 8 * j;
                float v1 = PSf[r * PS_LD + lane];
                float v2 = (lane < 8) ? PSf[r * PS_LD + 32 + lane] : -3.4e38f;
                float m = fmaxf(v1, v2);
                #pragma unroll
                for (int o = 16; o; o >>= 1)
                    m = fmaxf(m, __shfl_xor_sync(0xffffffffu, m, o));
                float e1 = __expf(v1 - m);
                float e2 = (lane < 8) ? __expf(v2 - m) : 0.f;
                float s = e1 + e2;
                #pragma unroll
                for (int o = 16; o; o >>= 1)
                    s += __shfl_xor_sync(0xffffffffu, s, o);
                float inv = 1.f / s;
                __nv_bfloat16 ph, pl;
                split1(e1 * inv, ph, pl);
                PH[r * XT_LD + lane] = ph;
                PL[r * XT_LD + lane] = pl;
                if (lane < 8) {
                    split1(e2 * inv, ph, pl);
                    PH[r * XT_LD + 32 + lane] = ph;
                    PL[r * XT_LD + 32 + lane] = pl;
                    PH[r * XT_LD + 40 + lane] = __ushort_as_bfloat16(0);
                    PL[r * XT_LD + 40 + lane] = __ushort_as_bfloat16(0);
                }
            }
        }
        __syncthreads();

        // ==== GEMM3: out = attn @ V + RS ; relu ; store (n-tile = w) ====
        {
            int nc = w * 8;
            float oacc[3][4];
            #pragma unroll
            for (int mt = 0; mt < 3; mt++)
                #pragma unroll
                for (int q = 0; q < 4; q++) oacc[mt][q] = 0.f;
            #pragma unroll
            for (int kt = 0; kt < 3; kt++) {
                uint32_t ah[3][4], al[3][4];
                #pragma unroll
                for (int mt = 0; mt < 3; mt++) {
                    uint32_t a0 = sb + TH_OFF +
                        ((mt * 16 + lr) * XT_LD + kt * 16) * 2 + (lq << 4);
                    ldsm4(a0, ah[mt]);
                    ldsm4(a0 + 6912, al[mt]);
                }
                uint32_t bb = sb + VH_OFF + ((kt * 16 + lr) * XA_LD + nc) * 2;
                uint32_t bh[2], bl[2];
                ldsm2t(bb, bh);
                ldsm2t(bb + 6912, bl);
                #pragma unroll
                for (int mt = 0; mt < 3; mt++) {
                    mma16816(oacc[mt], ah[mt], bh);
                    mma16816(oacc[mt], al[mt], bh);
                    mma16816(oacc[mt], ah[mt], bl);
                }
            }
            int c = nc + col2;
            float* ob = out + (size_t)b * (F_DIM * 256) + h * 64 + c;
            #pragma unroll
            for (int mt = 0; mt < 3; mt++) {
                int f0 = mt * 16 + row4, f1 = f0 + 8;
                float2 rs0 = *reinterpret_cast<const float2*>(RSf + f0 * RS_LD + c);
                *reinterpret_cast<float2*>(ob + f0 * 256) =
                    make_float2(fmaxf(oacc[mt][0] + rs0.x, 0.f),
                                fmaxf(oacc[mt][1] + rs0.y, 0.f));
                if (f1 < F_DIM) {
                    float2 rs1 = *reinterpret_cast<const float2*>(RSf + f1 * RS_LD + c);
                    *reinterpret_cast<float2*>(ob + f1 * 256) =
                        make_float2(fmaxf(oacc[mt][2] + rs1.x, 0.f),
                                    fmaxf(oacc[mt][3] + rs1.y, 0.f));
                }
            }
        }
    }
}

// ----------------------------------------------------------------------------
extern "C" void kernel_launch(void* const* d_in, const int* in_sizes, int n_in,
                              void* d_out, int out_size) {
    const float* X    = (const float*)d_in[0];
    const float* Wq   = (const float*)d_in[1];
    const float* Wk   = (const float*)d_in[2];
    const float* Wv   = (const float*)d_in[3];
    const float* Wres = (const float*)d_in[4];
    float* out = (float*)d_out;

    cudaFuncSetAttribute(attn_main_kernel,
                         cudaFuncAttributeMaxDynamicSharedMemorySize, SMEM_BYTES);

    precompute_kernel<<<H_DIM, 256>>>(Wq, Wk, Wv, Wres);
    attn_main_kernel<<<B_DIM, 256, SMEM_BYTES>>>(X, out);
}

// round 10
// speedup vs baseline: 2.3410x; 1.2694x over previous
#include <cuda_runtime.h>
#include <cuda_bf16.h>
#include <cstdint>

// ============================================================================
// AutoInt MHA — round 10: split-bf16 mma.sync, two independent 4-warp halves.
//  * half hp (warps 4hp..4hp+3) processes heads 2hp, 2hp+1 with named barriers
//    -> A-frag ldsm duplication x4 instead of x8, halves overlap each other.
//  * GEMM1 B operand (M | Wv | Wres) read as pre-built fragment-ordered gmem
//    image (LDG.128/lane, L2-resident) -> no weight SMEM, no staging.
//  * Residual accumulators persist in registers from GEMM1 to GEMM3 epilogue
//    (same warp owns same output columns) -> no RS buffer.
//  * hi/lo B-tiles of XT and V loaded with one ldmatrix.x4.trans each.
// scores = X (Wq Wk^T) X^T (M precomputed). 3-term split: AhBh+AlBh+AhBl.
// ============================================================================

#define B_DIM 4096
#define H_DIM 4

// ---- smem (bytes) ----
#define SM_XH   0u          // [48][72] bf16 (rows 40-47 zero)
#define SM_XL   6912u
#define SM_XTH  13824u      // [64][56] bf16 (cols 40-47 zero)
#define SM_XTL  20992u
#define SM_HALF 28160u      // + hp*HALF_SZ
#define HO_TH   0u          // [48][72] bf16 (PH [48][56] aliases after softmax)
#define HO_TL   6912u
#define HO_VH   13824u      // [48][72] bf16
#define HO_VL   20736u
#define HO_PS   27648u      // fp32 [40][52]
#define HALF_SZ 35968u
#define SMEM_BYTES (28160u + 2u * HALF_SZ)   // 100096 -> 2 CTAs/SM

// fragment image: [h][kt][nt] x 32 lanes x 16B  (nt: 0-7 T, 8-15 V, 16-23 R)
__device__ __align__(16) uint4 g_Bimg[H_DIM * 4 * 24 * 32];

// ---- PTX helpers -----------------------------------------------------------
__device__ __forceinline__ uint32_t cvta_smem(const void* p) {
    uint32_t a;
    asm("{ .reg .u64 t; cvta.to.shared.u64 t, %1; cvt.u32.u64 %0, t; }"
        : "=r"(a) : "l"(p));
    return a;
}
__device__ __forceinline__ void ldsm4(uint32_t a, uint32_t r[4]) {
    asm volatile("ldmatrix.sync.aligned.m8n8.x4.shared.b16 {%0,%1,%2,%3}, [%4];"
        : "=r"(r[0]), "=r"(r[1]), "=r"(r[2]), "=r"(r[3]) : "r"(a));
}
__device__ __forceinline__ void ldsm4t(uint32_t a, uint32_t r[4]) {
    asm volatile("ldmatrix.sync.aligned.m8n8.x4.trans.shared.b16 {%0,%1,%2,%3}, [%4];"
        : "=r"(r[0]), "=r"(r[1]), "=r"(r[2]), "=r"(r[3]) : "r"(a));
}
__device__ __forceinline__ void mma16816(float c[4], const uint32_t a[4],
                                         const uint32_t b0, const uint32_t b1) {
    asm volatile(
        "mma.sync.aligned.m16n8k16.row.col.f32.bf16.bf16.f32 "
        "{%0,%1,%2,%3}, {%4,%5,%6,%7}, {%8,%9}, {%0,%1,%2,%3};"
        : "+f"(c[0]), "+f"(c[1]), "+f"(c[2]), "+f"(c[3])
        : "r"(a[0]), "r"(a[1]), "r"(a[2]), "r"(a[3]), "r"(b0), "r"(b1));
}
__device__ __forceinline__ void split1(float x, float& h, float& l) {
    h = __bfloat162float(__float2bfloat16(x));
    l = x - h;
}
__device__ __forceinline__ uint32_t packh(float a, float b) {
    return (uint32_t)__bfloat16_as_ushort(__float2bfloat16(a)) |
           ((uint32_t)__bfloat16_as_ushort(__float2bfloat16(b)) << 16);
}
__device__ __forceinline__ uint32_t packl(float a, float b) {
    float ah = __bfloat162float(__float2bfloat16(a));
    float bh = __bfloat162float(__float2bfloat16(b));
    return packh(a - ah, b - bh);
}
#define BARH(hp) asm volatile("bar.sync %0, 128;" :: "r"((hp) + 1) : "memory")

// ----------------------------------------------------------------------------
// Precompute: M_h = Wq_h Wk_h^T; emit fragment-ordered hi/lo B image.
// grid = H, block = 256.
// ----------------------------------------------------------------------------
__global__ void precompute_kernel(const float* __restrict__ Wq,
                                  const float* __restrict__ Wk,
                                  const float* __restrict__ Wv,
                                  const float* __restrict__ Wres) {
    int h = blockIdx.x;
    __shared__ float sq[4096], sk[4096], sM[4096];
    for (int i = threadIdx.x; i < 4096; i += 256) {
        sq[i] = Wq[h * 4096 + i];
        sk[i] = Wk[h * 4096 + i];
    }
    __syncthreads();
    for (int idx = threadIdx.x; idx < 4096; idx += 256) {
        int e = idx >> 6, n = idx & 63;
        float s = 0.f;
        #pragma unroll 8
        for (int a = 0; a < 64; a++)
            s = fmaf(sq[e * 64 + a], sk[n * 64 + a], s);
        sM[e * 64 + n] = s;
    }
    __syncthreads();
    // 4 kt x 24 nt x 32 lanes
    for (int t = threadIdx.x; t < 3072; t += 256) {
        int kt = t / 768, rem = t % 768;
        int nt = rem >> 5, lane = rem & 31;
        int gid = lane >> 2, tig = lane & 3;
        int n8 = nt * 8 + gid;
        int ks = kt * 16 + tig * 2;
        float v[4];
        #pragma unroll
        for (int q = 0; q < 4; q++) {
            int k = ks + (q >> 1) * 8 + (q & 1);
            float val;
            if (nt < 8)        val = sM[k * 64 + n8];
            else if (nt < 16)  val = Wv[h * 4096 + k * 64 + (n8 - 64)];
            else               val = Wres[k * 256 + h * 64 + (n8 - 128)];
            v[q] = val;
        }
        uint4 img;
        img.x = packh(v[0], v[1]);
        img.y = packh(v[2], v[3]);
        img.z = packl(v[0], v[1]);
        img.w = packl(v[2], v[3]);
        g_Bimg[((h * 4 + kt) * 24 + nt) * 32 + lane] = img;
    }
}

// ----------------------------------------------------------------------------
__global__ void __launch_bounds__(256, 2)
attn_main_kernel(const float* __restrict__ Xg, float* __restrict__ out) {
    extern __shared__ char sm[];
    const uint32_t sb = cvta_smem(sm);

    const int tid  = threadIdx.x;
    const int b    = blockIdx.x;
    const int w    = tid >> 5;
    const int lane = tid & 31;
    const int hp   = w >> 2;            // half 0/1
    const int wq   = w & 3;             // warp within half
    const int lr   = lane & 15;
    const int lq   = lane >> 4;
    const int row4 = lane >> 2;
    const int col2 = 2 * (lane & 3);

    const uint32_t HB = SM_HALF + (uint32_t)hp * HALF_SZ;   // half base (bytes)
    float* PSf = (float*)(sm + HB + HO_PS);

    // ---- zero X region (pads must be 0) ----
    for (int i = tid; i < (int)(SM_HALF / 16); i += 256)
        reinterpret_cast<uint4*>(sm)[i] = make_uint4(0, 0, 0, 0);
    __syncthreads();

    // ---- stage X: split hi/lo + transposed ----
    {
        const float4* xb = reinterpret_cast<const float4*>(Xg + (size_t)b * 2560);
        __nv_bfloat16* XH  = (__nv_bfloat16*)(sm + SM_XH);
        __nv_bfloat16* XL  = (__nv_bfloat16*)(sm + SM_XL);
        __nv_bfloat16* XTH = (__nv_bfloat16*)(sm + SM_XTH);
        __nv_bfloat16* XTL = (__nv_bfloat16*)(sm + SM_XTL);
        for (int i = tid; i < 640; i += 256) {
            float4 v = xb[i];
            int f = i >> 4, e0 = (i & 15) * 4;
            float vv[4] = {v.x, v.y, v.z, v.w};
            #pragma unroll
            for (int j = 0; j < 4; j++) {
                float hi, lo;
                split1(vv[j], hi, lo);
                int e = e0 + j;
                XH[f * 72 + e] = __float2bfloat16(hi);
                XL[f * 72 + e] = __float2bfloat16(lo);
                XTH[e * 56 + f] = __float2bfloat16(hi);
                XTL[e * 56 + f] = __float2bfloat16(lo);
            }
        }
    }
    __syncthreads();

    for (int hh = 0; hh < 2; hh++) {
        const int h = hp * 2 + hh;

        // ==== GEMM1: T|V|R = X @ [M|Wv|WresBlk], B frags via LDG ====
        float tac[3][2][4], vac[3][2][4], rac[3][2][4];
        #pragma unroll
        for (int mt = 0; mt < 3; mt++)
            #pragma unroll
            for (int jj = 0; jj < 2; jj++)
                #pragma unroll
                for (int q = 0; q < 4; q++)
                    tac[mt][jj][q] = vac[mt][jj][q] = rac[mt][jj][q] = 0.f;

        #pragma unroll
        for (int kt = 0; kt < 4; kt++) {
            uint32_t ah[3][4], al[3][4];
            #pragma unroll
            for (int mt = 0; mt < 3; mt++) {
                uint32_t a0 = sb + SM_XH + ((mt * 16 + lr) * 72 + kt * 16) * 2 + (lq << 4);
                ldsm4(a0, ah[mt]);
                ldsm4(a0 + (SM_XL - SM_XH), al[mt]);
            }
            #pragma unroll
            for (int mat = 0; mat < 3; mat++) {
                #pragma unroll
                for (int jj = 0; jj < 2; jj++) {
                    int nt = mat * 8 + 2 * wq + jj;
                    uint4 bb = g_Bimg[((h * 4 + kt) * 24 + nt) * 32 + lane];
                    float (*acc)[4] = (mat == 0) ? tac[0] : (mat == 1) ? vac[0] : rac[0];
                    #pragma unroll
                    for (int mt = 0; mt < 3; mt++) {
                        float* c = acc[mt * 2 + jj];
                        mma16816(c, ah[mt], bb.x, bb.y);
                        mma16816(c, al[mt], bb.x, bb.y);
                        mma16816(c, ah[mt], bb.z, bb.w);
                    }
                }
            }
        }
        // epilogue: T,V -> smem split (R stays in registers)
        #pragma unroll
        for (int jj = 0; jj < 2; jj++) {
            int c = 16 * wq + 8 * jj + col2;
            #pragma unroll
            for (int mt = 0; mt < 3; mt++) {
                int r0 = mt * 16 + row4, r1 = r0 + 8;
                const float* tt = tac[mt][jj];
                const float* vv = vac[mt][jj];
                *(uint32_t*)(sm + HB + HO_TH + (r0 * 72 + c) * 2) = packh(tt[0], tt[1]);
                *(uint32_t*)(sm + HB + HO_TL + (r0 * 72 + c) * 2) = packl(tt[0], tt[1]);
                *(uint32_t*)(sm + HB + HO_TH + (r1 * 72 + c) * 2) = packh(tt[2], tt[3]);
                *(uint32_t*)(sm + HB + HO_TL + (r1 * 72 + c) * 2) = packl(tt[2], tt[3]);
                *(uint32_t*)(sm + HB + HO_VH + (r0 * 72 + c) * 2) = packh(vv[0], vv[1]);
                *(uint32_t*)(sm + HB + HO_VL + (r0 * 72 + c) * 2) = packl(vv[0], vv[1]);
                *(uint32_t*)(sm + HB + HO_VH + (r1 * 72 + c) * 2) = packh(vv[2], vv[3]);
                *(uint32_t*)(sm + HB + HO_VL + (r1 * 72 + c) * 2) = packl(vv[2], vv[3]);
            }
        }
        BARH(hp);

        // ==== scores: PS = T @ X^T   (warps 0-2: mt = wq) ====
        if (wq < 3) {
            const int mt = wq;
            float sacc[6][4];
            #pragma unroll
            for (int j = 0; j < 6; j++)
                #pragma unroll
                for (int q = 0; q < 4; q++) sacc[j][q] = 0.f;
            #pragma unroll
            for (int kt = 0; kt < 4; kt++) {
                uint32_t ah[4], al[4];
                uint32_t a0 = sb + HB + HO_TH + ((mt * 16 + lr) * 72 + kt * 16) * 2 + (lq << 4);
                ldsm4(a0, ah);
                ldsm4(a0 + (HO_TL - HO_TH), al);
                #pragma unroll
                for (int j = 0; j < 6; j++) {
                    uint32_t bt[4];
                    uint32_t badr = sb + ((lane < 16) ? SM_XTH : SM_XTL) +
                                    ((kt * 16 + lr) * 56 + j * 8) * 2;
                    ldsm4t(badr, bt);
                    mma16816(sacc[j], ah, bt[0], bt[1]);
                    mma16816(sacc[j], al, bt[0], bt[1]);
                    mma16816(sacc[j], ah, bt[2], bt[3]);
                }
            }
            #pragma unroll
            for (int j = 0; j < 6; j++) {
                int c = 8 * j + col2;
                int r0 = mt * 16 + row4, r1 = r0 + 8;
                *(float2*)(PSf + r0 * 52 + c) = make_float2(sacc[j][0], sacc[j][1]);
                if (r1 < 40)
                    *(float2*)(PSf + r1 * 52 + c) = make_float2(sacc[j][2], sacc[j][3]);
            }
        }
        BARH(hp);

        // ==== softmax -> PH/PL (alias TH/TL, stride 56), zero cols 40-47 ====
        {
            __nv_bfloat16* PH = (__nv_bfloat16*)(sm + HB + HO_TH);
            __nv_bfloat16* PL = (__nv_bfloat16*)(sm + HB + HO_TL);
            #pragma unroll
            for (int j = 0; j < 10; j++) {
                int r = wq + 4 * j;
                float v1 = PSf[r * 52 + lane];
                float v2 = (lane < 8) ? PSf[r * 52 + 32 + lane] : -3.4e38f;
                float m = fmaxf(v1, v2);
                #pragma unroll
                for (int o = 16; o; o >>= 1)
                    m = fmaxf(m, __shfl_xor_sync(0xffffffffu, m, o));
                float e1 = __expf(v1 - m);
                float e2 = (lane < 8) ? __expf(v2 - m) : 0.f;
                float s = e1 + e2;
                #pragma unroll
                for (int o = 16; o; o >>= 1)
                    s += __shfl_xor_sync(0xffffffffu, s, o);
                float inv = 1.f / s;
                float p1 = e1 * inv, p1h, p1l;
                split1(p1, p1h, p1l);
                PH[r * 56 + lane] = __float2bfloat16(p1h);
                PL[r * 56 + lane] = __float2bfloat16(p1l);
                if (lane < 8) {
                    float p2 = e2 * inv, p2h, p2l;
                    split1(p2, p2h, p2l);
                    PH[r * 56 + 32 + lane] = __float2bfloat16(p2h);
                    PL[r * 56 + 32 + lane] = __float2bfloat16(p2l);
                    PH[r * 56 + 40 + lane] = __ushort_as_bfloat16(0);
                    PL[r * 56 + 40 + lane] = __ushort_as_bfloat16(0);
                }
            }
        }
        BARH(hp);

        // ==== GEMM3: out = attn @ V + R(regs); relu; store ====
        {
            float oacc[3][2][4];
            #pragma unroll
            for (int mt = 0; mt < 3; mt++)
                #pragma unroll
                for (int jj = 0; jj < 2; jj++)
                    #pragma unroll
                    for (int q = 0; q < 4; q++) oacc[mt][jj][q] = 0.f;
            #pragma unroll
            for (int kt = 0; kt < 3; kt++) {
                uint32_t ah[3][4], al[3][4];
                #pragma unroll
                for (int mt = 0; mt < 3; mt++) {
                    uint32_t a0 = sb + HB + HO_TH +
                                  ((mt * 16 + lr) * 56 + kt * 16) * 2 + (lq << 4);
                    ldsm4(a0, ah[mt]);
                    ldsm4(a0 + (HO_TL - HO_TH), al[mt]);
                }
                #pragma unroll
                for (int jj = 0; jj < 2; jj++) {
                    int nc = 16 * wq + 8 * jj;
                    uint32_t bt[4];
                    uint32_t badr = sb + HB + ((lane < 16) ? HO_VH : HO_VL) +
                                    ((kt * 16 + lr) * 72 + nc) * 2;
                    ldsm4t(badr, bt);
                    #pragma unroll
                    for (int mt = 0; mt < 3; mt++) {
                        mma16816(oacc[mt][jj], ah[mt], bt[0], bt[1]);
                        mma16816(oacc[mt][jj], al[mt], bt[0], bt[1]);
                        mma16816(oacc[mt][jj], ah[mt], bt[2], bt[3]);
                    }
                }
            }
            float* ob = out + (size_t)b * (40 * 256) + h * 64;
            #pragma unroll
            for (int jj = 0; jj < 2; jj++) {
                int c = 16 * wq + 8 * jj + col2;
                #pragma unroll
                for (int mt = 0; mt < 3; mt++) {
                    int r0 = mt * 16 + row4, r1 = r0 + 8;
                    const float* oa = oacc[mt][jj];
                    const float* rr = rac[mt][jj];
                    if (r0 < 40)
                        *(float2*)(ob + r0 * 256 + c) =
                            make_float2(fmaxf(oa[0] + rr[0], 0.f),
                                        fmaxf(oa[1] + rr[1], 0.f));
                    if (r1 < 40)
                        *(float2*)(ob + r1 * 256 + c) =
                            make_float2(fmaxf(oa[2] + rr[2], 0.f),
                                        fmaxf(oa[3] + rr[3], 0.f));
                }
            }
        }
        BARH(hp);   // protect TH/TL/VH/VL before next head's GEMM1 rewrites
    }
}

// ----------------------------------------------------------------------------
extern "C" void kernel_launch(void* const* d_in, const int* in_sizes, int n_in,
                              void* d_out, int out_size) {
    const float* X    = (const float*)d_in[0];
    const float* Wq   = (const float*)d_in[1];
    const float* Wk   = (const float*)d_in[2];
    const float* Wv   = (const float*)d_in[3];
    const float* Wres = (const float*)d_in[4];
    float* out = (float*)d_out;

    cudaFuncSetAttribute(attn_main_kernel,
                         cudaFuncAttributeMaxDynamicSharedMemorySize, SMEM_BYTES);

    precompute_kernel<<<H_DIM, 256>>>(Wq, Wk, Wv, Wres);
    attn_main_kernel<<<B_DIM, 256, SMEM_BYTES>>>(X, out);
}

// round 13
// speedup vs baseline: 3.0853x; 1.3179x over previous
#include <cuda_runtime.h>
#include <cuda_bf16.h>
#include <cstdint>

// ============================================================================
// AutoInt MHA — round 13: round-12 structure + RACE FIX.
// Bug in r11/r12: softmax PH-writes (stride 56) alias TH (stride 72) that
// other warps were still reading for scores A-tiles. Fix: scores+softmax
// compute phase and PH/PL write phase separated by __syncthreads(); p-values
// carried in registers across the barrier.
//  * CTA = (batch, head pair), 128 thr, grid 8192, 4 CTAs/SM.
//  * GEMM1/residual B operands from fragment-ordered gmem image (L2-resident).
//  * residual accumulated straight into GEMM3's oacc; scores n-tiles 0-4 only.
// scores = X (Wq Wk^T) X^T (M precomputed). 3-term split: AhBh+AlBh+AhBl.
// ============================================================================

#define H_DIM 4

// ---- smem (bytes) ----
#define SM_XH  0u        // [48][72] bf16 (rows 40-47 zero)
#define SM_XL  6912u
#define SM_XTH 13824u    // [64][56] bf16 (X^T, k rows)
#define SM_XTL 20992u
#define SM_TH  28160u    // [48][72] bf16; PH [40][56] aliases after softmax
#define SM_TL  35072u
#define SM_VH  41984u    // [48][72] bf16 (rows 40-47 exact zero)
#define SM_VL  48896u
#define SMEM_BYTES 55808u   // 4 CTAs/SM

// fragment image: [h][kt][nt] x 32 lanes x 16B  (nt: 0-7 T, 8-15 V, 16-23 R)
__device__ __align__(16) uint4 g_Bimg[H_DIM * 4 * 24 * 32];

// ---- PTX helpers -----------------------------------------------------------
__device__ __forceinline__ uint32_t cvta_smem(const void* p) {
    uint32_t a;
    asm("{ .reg .u64 t; cvta.to.shared.u64 t, %1; cvt.u32.u64 %0, t; }"
        : "=r"(a) : "l"(p));
    return a;
}
__device__ __forceinline__ void ldsm4(uint32_t a, uint32_t r[4]) {
    asm volatile("ldmatrix.sync.aligned.m8n8.x4.shared.b16 {%0,%1,%2,%3}, [%4];"
        : "=r"(r[0]), "=r"(r[1]), "=r"(r[2]), "=r"(r[3]) : "r"(a));
}
__device__ __forceinline__ void ldsm4t(uint32_t a, uint32_t r[4]) {
    asm volatile("ldmatrix.sync.aligned.m8n8.x4.trans.shared.b16 {%0,%1,%2,%3}, [%4];"
        : "=r"(r[0]), "=r"(r[1]), "=r"(r[2]), "=r"(r[3]) : "r"(a));
}
__device__ __forceinline__ void mma16816(float c[4], const uint32_t a[4],
                                         const uint32_t b0, const uint32_t b1) {
    asm volatile(
        "mma.sync.aligned.m16n8k16.row.col.f32.bf16.bf16.f32 "
        "{%0,%1,%2,%3}, {%4,%5,%6,%7}, {%8,%9}, {%0,%1,%2,%3};"
        : "+f"(c[0]), "+f"(c[1]), "+f"(c[2]), "+f"(c[3])
        : "r"(a[0]), "r"(a[1]), "r"(a[2]), "r"(a[3]), "r"(b0), "r"(b1));
}
__device__ __forceinline__ void split1(float x, float& h, float& l) {
    h = __bfloat162float(__float2bfloat16(x));
    l = x - h;
}
__device__ __forceinline__ uint32_t packh(float a, float b) {
    return (uint32_t)__bfloat16_as_ushort(__float2bfloat16(a)) |
           ((uint32_t)__bfloat16_as_ushort(__float2bfloat16(b)) << 16);
}
__device__ __forceinline__ uint32_t packl(float a, float b) {
    float ah = __bfloat162float(__float2bfloat16(a));
    float bh = __bfloat162float(__float2bfloat16(b));
    return packh(a - ah, b - bh);
}

// ----------------------------------------------------------------------------
// Precompute: M_h = Wq_h Wk_h^T; emit fragment-ordered hi/lo B image.
// ----------------------------------------------------------------------------
__global__ void precompute_kernel(const float* __restrict__ Wq,
                                  const float* __restrict__ Wk,
                                  const float* __restrict__ Wv,
                                  const float* __restrict__ Wres) {
    int h = blockIdx.x;
    __shared__ float sq[4096], sk[4096], sM[4096];
    for (int i = threadIdx.x; i < 4096; i += 256) {
        sq[i] = Wq[h * 4096 + i];
        sk[i] = Wk[h * 4096 + i];
    }
    __syncthreads();
    for (int idx = threadIdx.x; idx < 4096; idx += 256) {
        int e = idx >> 6, n = idx & 63;
        float s = 0.f;
        #pragma unroll 8
        for (int a = 0; a < 64; a++)
            s = fmaf(sq[e * 64 + a], sk[n * 64 + a], s);
        sM[e * 64 + n] = s;
    }
    __syncthreads();
    for (int t = threadIdx.x; t < 3072; t += 256) {
        int kt = t / 768, rem = t % 768;
        int nt = rem >> 5, lane = rem & 31;
        int gid = lane >> 2, tig = lane & 3;
        int n8 = nt * 8 + gid;
        int ks = kt * 16 + tig * 2;
        float v[4];
        #pragma unroll
        for (int q = 0; q < 4; q++) {
            int k = ks + (q >> 1) * 8 + (q & 1);
            float val;
            if (nt < 8)        val = sM[k * 64 + n8];
            else if (nt < 16)  val = Wv[h * 4096 + k * 64 + (n8 - 64)];
            else               val = Wres[k * 256 + h * 64 + (n8 - 128)];
            v[q] = val;
        }
        uint4 img;
        img.x = packh(v[0], v[1]);
        img.y = packh(v[2], v[3]);
        img.z = packl(v[0], v[1]);
        img.w = packl(v[2], v[3]);
        g_Bimg[((h * 4 + kt) * 24 + nt) * 32 + lane] = img;
    }
}

// ----------------------------------------------------------------------------
__global__ void __launch_bounds__(128, 4)
attn_main_kernel(const float* __restrict__ Xg, float* __restrict__ out) {
    extern __shared__ char sm[];
    const uint32_t sb = cvta_smem(sm);

    const int tid  = threadIdx.x;
    const int w    = tid >> 5;          // warp 0-3
    const int lane = tid & 31;
    const int b    = blockIdx.x >> 1;   // batch
    const int hp   = blockIdx.x & 1;    // head pair
    const int lr   = lane & 15;
    const int lq   = lane >> 4;
    const int row4 = lane >> 2;
    const int col2 = 2 * (lane & 3);

    // ---- zero X pad rows 40-47 (both bufs) ----
    for (int i = tid; i < 144; i += 128) {
        int buf = i / 72, j = i % 72;
        *(uint4*)(sm + (buf ? SM_XL : SM_XH) + (40 + j / 9) * 144 + (j % 9) * 16) =
            make_uint4(0, 0, 0, 0);
    }
    // ---- stage X split hi/lo + transposed XT hi/lo ----
    {
        const float4* xb = reinterpret_cast<const float4*>(Xg + (size_t)b * 2560);
        __nv_bfloat16* XH  = (__nv_bfloat16*)(sm + SM_XH);
        __nv_bfloat16* XL  = (__nv_bfloat16*)(sm + SM_XL);
        __nv_bfloat16* XTH = (__nv_bfloat16*)(sm + SM_XTH);
        __nv_bfloat16* XTL = (__nv_bfloat16*)(sm + SM_XTL);
        for (int i = tid; i < 640; i += 128) {
            float4 v = xb[i];
            int f = i >> 4, e0 = (i & 15) * 4;
            float vv[4] = {v.x, v.y, v.z, v.w};
            #pragma unroll
            for (int j = 0; j < 4; j++) {
                float hi, lo;
                split1(vv[j], hi, lo);
                int e = e0 + j;
                XH[f * 72 + e] = __float2bfloat16(hi);
                XL[f * 72 + e] = __float2bfloat16(lo);
                XTH[e * 56 + f] = __float2bfloat16(hi);
                XTL[e * 56 + f] = __float2bfloat16(lo);
            }
        }
    }
    __syncthreads();

    for (int hh = 0; hh < 2; hh++) {
        const int h = hp * 2 + hh;

        // ==== GEMM1: T|V = X @ [M|Wv]  (B frags via LDG, L2-resident) ====
        float tac[3][2][4], vac[3][2][4];
        #pragma unroll
        for (int mt = 0; mt < 3; mt++)
            #pragma unroll
            for (int jj = 0; jj < 2; jj++)
                #pragma unroll
                for (int q = 0; q < 4; q++)
                    tac[mt][jj][q] = vac[mt][jj][q] = 0.f;
        #pragma unroll
        for (int kt = 0; kt < 4; kt++) {
            uint32_t ah[3][4], al[3][4];
            #pragma unroll
            for (int mt = 0; mt < 3; mt++) {
                uint32_t a0 = sb + SM_XH + ((mt * 16 + lr) * 72 + kt * 16) * 2 + (lq << 4);
                ldsm4(a0, ah[mt]);
                ldsm4(a0 + (SM_XL - SM_XH), al[mt]);
            }
            #pragma unroll
            for (int mat = 0; mat < 2; mat++) {
                #pragma unroll
                for (int jj = 0; jj < 2; jj++) {
                    int nt = mat * 8 + 2 * w + jj;
                    uint4 bb = g_Bimg[((h * 4 + kt) * 24 + nt) * 32 + lane];
                    #pragma unroll
                    for (int mt = 0; mt < 3; mt++) {
                        float* c = (mat == 0) ? tac[mt][jj] : vac[mt][jj];
                        mma16816(c, ah[mt], bb.x, bb.y);
                        mma16816(c, al[mt], bb.x, bb.y);
                        mma16816(c, ah[mt], bb.z, bb.w);
                    }
                }
            }
        }
        // epilogue: T,V -> smem split
        #pragma unroll
        for (int jj = 0; jj < 2; jj++) {
            int c = 16 * w + 8 * jj + col2;
            #pragma unroll
            for (int mt = 0; mt < 3; mt++) {
                int r0 = mt * 16 + row4, r1 = r0 + 8;
                const float* tt = tac[mt][jj];
                const float* vv = vac[mt][jj];
                *(uint32_t*)(sm + SM_TH + (r0 * 72 + c) * 2) = packh(tt[0], tt[1]);
                *(uint32_t*)(sm + SM_TL + (r0 * 72 + c) * 2) = packl(tt[0], tt[1]);
                *(uint32_t*)(sm + SM_TH + (r1 * 72 + c) * 2) = packh(tt[2], tt[3]);
                *(uint32_t*)(sm + SM_TL + (r1 * 72 + c) * 2) = packl(tt[2], tt[3]);
                *(uint32_t*)(sm + SM_VH + (r0 * 72 + c) * 2) = packh(vv[0], vv[1]);
                *(uint32_t*)(sm + SM_VL + (r0 * 72 + c) * 2) = packl(vv[0], vv[1]);
                *(uint32_t*)(sm + SM_VH + (r1 * 72 + c) * 2) = packh(vv[2], vv[3]);
                *(uint32_t*)(sm + SM_VL + (r1 * 72 + c) * 2) = packl(vv[2], vv[3]);
            }
        }

        // ==== residual pass: oacc = X @ WresBlk (independent of T/V) ====
        float oacc[3][2][4];
        #pragma unroll
        for (int mt = 0; mt < 3; mt++)
            #pragma unroll
            for (int jj = 0; jj < 2; jj++)
                #pragma unroll
                for (int q = 0; q < 4; q++) oacc[mt][jj][q] = 0.f;
        #pragma unroll
        for (int kt = 0; kt < 4; kt++) {
            uint4 bb0 = g_Bimg[((h * 4 + kt) * 24 + 16 + 2 * w) * 32 + lane];
            uint4 bb1 = g_Bimg[((h * 4 + kt) * 24 + 17 + 2 * w) * 32 + lane];
            #pragma unroll
            for (int mt = 0; mt < 3; mt++) {
                uint32_t ah[4], al[4];
                uint32_t a0 = sb + SM_XH + ((mt * 16 + lr) * 72 + kt * 16) * 2 + (lq << 4);
                ldsm4(a0, ah);
                ldsm4(a0 + (SM_XL - SM_XH), al);
                mma16816(oacc[mt][0], ah, bb0.x, bb0.y);
                mma16816(oacc[mt][0], al, bb0.x, bb0.y);
                mma16816(oacc[mt][0], ah, bb0.z, bb0.w);
                mma16816(oacc[mt][1], ah, bb1.x, bb1.y);
                mma16816(oacc[mt][1], al, bb1.x, bb1.y);
                mma16816(oacc[mt][1], ah, bb1.z, bb1.w);
            }
        }
        __syncthreads();   // GEMM1 epilogue visible before scores reads

        // ==== PHASE A (warps 0-2): scores MMAs + softmax COMPUTE (regs) ====
        float sacc[5][4];
        float inv0 = 0.f, inv1 = 0.f;
        if (w < 3) {
            #pragma unroll
            for (int j = 0; j < 5; j++)
                #pragma unroll
                for (int q = 0; q < 4; q++) sacc[j][q] = 0.f;
            #pragma unroll
            for (int kt = 0; kt < 4; kt++) {
                uint32_t ah[4], al[4];
                uint32_t a0 = sb + SM_TH + ((w * 16 + lr) * 72 + kt * 16) * 2 + (lq << 4);
                ldsm4(a0, ah);
                ldsm4(a0 + (SM_TL - SM_TH), al);
                #pragma unroll
                for (int j = 0; j < 5; j++) {
                    uint32_t bt[4];     // verified: trans ldmatrix on XT k-rows
                    uint32_t badr = sb + ((lane < 16) ? SM_XTH : SM_XTL) +
                                    ((kt * 16 + lr) * 56 + j * 8) * 2;
                    ldsm4t(badr, bt);
                    mma16816(sacc[j], ah, bt[0], bt[1]);
                    mma16816(sacc[j], al, bt[0], bt[1]);
                    mma16816(sacc[j], ah, bt[2], bt[3]);
                }
            }
            float m0 = -3.4e38f, m1 = -3.4e38f;
            #pragma unroll
            for (int j = 0; j < 5; j++) {
                m0 = fmaxf(m0, fmaxf(sacc[j][0], sacc[j][1]));
                m1 = fmaxf(m1, fmaxf(sacc[j][2], sacc[j][3]));
            }
            m0 = fmaxf(m0, __shfl_xor_sync(0xffffffffu, m0, 1));
            m0 = fmaxf(m0, __shfl_xor_sync(0xffffffffu, m0, 2));
            m1 = fmaxf(m1, __shfl_xor_sync(0xffffffffu, m1, 1));
            m1 = fmaxf(m1, __shfl_xor_sync(0xffffffffu, m1, 2));
            float s0 = 0.f, s1 = 0.f;
            #pragma unroll
            for (int j = 0; j < 5; j++) {
                sacc[j][0] = __expf(sacc[j][0] - m0);
                sacc[j][1] = __expf(sacc[j][1] - m0);
                sacc[j][2] = __expf(sacc[j][2] - m1);
                sacc[j][3] = __expf(sacc[j][3] - m1);
                s0 += sacc[j][0] + sacc[j][1];
                s1 += sacc[j][2] + sacc[j][3];
            }
            s0 += __shfl_xor_sync(0xffffffffu, s0, 1);
            s0 += __shfl_xor_sync(0xffffffffu, s0, 2);
            s1 += __shfl_xor_sync(0xffffffffu, s1, 1);
            s1 += __shfl_xor_sync(0xffffffffu, s1, 2);
            inv0 = 1.f / s0;
            inv1 = 1.f / s1;
        }
        __syncthreads();   // RACE FIX: all TH/TL reads done before PH writes

        // ==== PHASE B (warps 0-2): write PH/PL (aliases TH/TL) ====
        if (w < 3) {
            int r0 = 16 * w + row4, r1 = r0 + 8;
            bool has1 = (r1 < 40);
            #pragma unroll
            for (int j = 0; j < 5; j++) {
                int c = 8 * j + col2;
                float p0 = sacc[j][0] * inv0, p0b = sacc[j][1] * inv0;
                *(uint32_t*)(sm + SM_TH + (r0 * 56 + c) * 2) = packh(p0, p0b);
                *(uint32_t*)(sm + SM_TL + (r0 * 56 + c) * 2) = packl(p0, p0b);
                if (has1) {
                    float p1 = sacc[j][2] * inv1, p1b = sacc[j][3] * inv1;
                    *(uint32_t*)(sm + SM_TH + (r1 * 56 + c) * 2) = packh(p1, p1b);
                    *(uint32_t*)(sm + SM_TL + (r1 * 56 + c) * 2) = packl(p1, p1b);
                }
            }
            {   // zero attn k-pad cols 40-47
                int c = 40 + col2;
                *(uint32_t*)(sm + SM_TH + (r0 * 56 + c) * 2) = 0u;
                *(uint32_t*)(sm + SM_TL + (r0 * 56 + c) * 2) = 0u;
                if (has1) {
                    *(uint32_t*)(sm + SM_TH + (r1 * 56 + c) * 2) = 0u;
                    *(uint32_t*)(sm + SM_TL + (r1 * 56 + c) * 2) = 0u;
                }
            }
        }
        __syncthreads();

        // ==== GEMM3: oacc += attn @ V ; relu ; store ====
        #pragma unroll
        for (int kt = 0; kt < 3; kt++) {
            uint32_t ah[3][4], al[3][4];
            #pragma unroll
            for (int mt = 0; mt < 3; mt++) {
                uint32_t a0 = sb + SM_TH + ((mt * 16 + lr) * 56 + kt * 16) * 2 + (lq << 4);
                ldsm4(a0, ah[mt]);
                ldsm4(a0 + (SM_TL - SM_TH), al[mt]);
            }
            #pragma unroll
            for (int jj = 0; jj < 2; jj++) {
                int nc = 16 * w + 8 * jj;
                uint32_t bt[4];
                uint32_t badr = sb + ((lane < 16) ? SM_VH : SM_VL) +
                                ((kt * 16 + lr) * 72 + nc) * 2;
                ldsm4t(badr, bt);
                #pragma unroll
                for (int mt = 0; mt < 3; mt++) {
                    mma16816(oacc[mt][jj], ah[mt], bt[0], bt[1]);
                    mma16816(oacc[mt][jj], al[mt], bt[0], bt[1]);
                    mma16816(oacc[mt][jj], ah[mt], bt[2], bt[3]);
                }
            }
        }
        {
            float* ob = out + (size_t)b * (40 * 256) + h * 64;
            #pragma unroll
            for (int jj = 0; jj < 2; jj++) {
                int c = 16 * w + 8 * jj + col2;
                #pragma unroll
                for (int mt = 0; mt < 3; mt++) {
                    int r0 = mt * 16 + row4, r1 = r0 + 8;
                    const float* oa = oacc[mt][jj];
                    *(float2*)(ob + r0 * 256 + c) =
                        make_float2(fmaxf(oa[0], 0.f), fmaxf(oa[1], 0.f));
                    if (r1 < 40)
                        *(float2*)(ob + r1 * 256 + c) =
                            make_float2(fmaxf(oa[2], 0.f), fmaxf(oa[3], 0.f));
                }
            }
        }
        __syncthreads();   // protect TH/TL/VH/VL before next head's GEMM1
    }
}

// ----------------------------------------------------------------------------
extern "C" void kernel_launch(void* const* d_in, const int* in_sizes, int n_in,
                              void* d_out, int out_size) {
    const float* X    = (const float*)d_in[0];
    const float* Wq   = (const float*)d_in[1];
    const float* Wk   = (const float*)d_in[2];
    const float* Wv   = (const float*)d_in[3];
    const float* Wres = (const float*)d_in[4];
    float* out = (float*)d_out;

    cudaFuncSetAttribute(attn_main_kernel,
                         cudaFuncAttributeMaxDynamicSharedMemorySize, SMEM_BYTES);

    precompute_kernel<<<H_DIM, 256>>>(Wq, Wk, Wv, Wres);
    attn_main_kernel<<<8192, 128, SMEM_BYTES>>>(X, out);
}

// round 14
// speedup vs baseline: 3.2587x; 1.0562x over previous
#include <cuda_runtime.h>
#include <cuda_bf16.h>
#include <cstdint>

// ============================================================================
// AutoInt MHA — round 14: round-13 (race-fixed) + non-trans scores-B.
// Single change vs r13: XTH/XTL deleted; scores B-fragments loaded from
// XH/XL with NON-trans ldmatrix.x4 (X's [f][e] layout IS the col-major B
// fragment for T @ X^T: thread t needs B[k=2(t%4)+j, n=t/4]; matrix rows
// n = 8j+(lane&7), k-offsets {XH:+0,+8, XL:+0,+8}). Smem 41.5 KB ->
// __launch_bounds__(128,5): 5 CTAs/SM, 20 warps.
//  * CTA = (batch, head pair), 128 thr, grid 8192.
//  * GEMM1/residual B operands from fragment-ordered gmem image (L2-resident).
//  * in-register softmax with phase-split (r13 race fix) over aliased PH/TH.
// scores = X (Wq Wk^T) X^T (M precomputed). 3-term split: AhBh+AlBh+AhBl.
// ============================================================================

#define H_DIM 4

// ---- smem (bytes) ----
#define SM_XH  0u        // [48][72] bf16 (rows 40-47 zero)
#define SM_XL  6912u
#define SM_TH  13824u    // [48][72] bf16; PH [40][56] aliases after softmax
#define SM_TL  20736u
#define SM_VH  27648u    // [48][72] bf16 (rows 40-47 exact zero)
#define SM_VL  34560u
#define SMEM_BYTES 41472u   // 5 CTAs/SM

// fragment image: [h][kt][nt] x 32 lanes x 16B  (nt: 0-7 T, 8-15 V, 16-23 R)
__device__ __align__(16) uint4 g_Bimg[H_DIM * 4 * 24 * 32];

// ---- PTX helpers -----------------------------------------------------------
__device__ __forceinline__ uint32_t cvta_smem(const void* p) {
    uint32_t a;
    asm("{ .reg .u64 t; cvta.to.shared.u64 t, %1; cvt.u32.u64 %0, t; }"
        : "=r"(a) : "l"(p));
    return a;
}
__device__ __forceinline__ void ldsm4(uint32_t a, uint32_t r[4]) {
    asm volatile("ldmatrix.sync.aligned.m8n8.x4.shared.b16 {%0,%1,%2,%3}, [%4];"
        : "=r"(r[0]), "=r"(r[1]), "=r"(r[2]), "=r"(r[3]) : "r"(a));
}
__device__ __forceinline__ void ldsm4t(uint32_t a, uint32_t r[4]) {
    asm volatile("ldmatrix.sync.aligned.m8n8.x4.trans.shared.b16 {%0,%1,%2,%3}, [%4];"
        : "=r"(r[0]), "=r"(r[1]), "=r"(r[2]), "=r"(r[3]) : "r"(a));
}
__device__ __forceinline__ void mma16816(float c[4], const uint32_t a[4],
                                         const uint32_t b0, const uint32_t b1) {
    asm volatile(
        "mma.sync.aligned.m16n8k16.row.col.f32.bf16.bf16.f32 "
        "{%0,%1,%2,%3}, {%4,%5,%6,%7}, {%8,%9}, {%0,%1,%2,%3};"
        : "+f"(c[0]), "+f"(c[1]), "+f"(c[2]), "+f"(c[3])
        : "r"(a[0]), "r"(a[1]), "r"(a[2]), "r"(a[3]), "r"(b0), "r"(b1));
}
__device__ __forceinline__ void split1(float x, float& h, float& l) {
    h = __bfloat162float(__float2bfloat16(x));
    l = x - h;
}
__device__ __forceinline__ uint32_t packh(float a, float b) {
    return (uint32_t)__bfloat16_as_ushort(__float2bfloat16(a)) |
           ((uint32_t)__bfloat16_as_ushort(__float2bfloat16(b)) << 16);
}
__device__ __forceinline__ uint32_t packl(float a, float b) {
    float ah = __bfloat162float(__float2bfloat16(a));
    float bh = __bfloat162float(__float2bfloat16(b));
    return packh(a - ah, b - bh);
}

// ----------------------------------------------------------------------------
// Precompute: M_h = Wq_h Wk_h^T; emit fragment-ordered hi/lo B image.
// ----------------------------------------------------------------------------
__global__ void precompute_kernel(const float* __restrict__ Wq,
                                  const float* __restrict__ Wk,
                                  const float* __restrict__ Wv,
                                  const float* __restrict__ Wres) {
    int h = blockIdx.x;
    __shared__ float sq[4096], sk[4096], sM[4096];
    for (int i = threadIdx.x; i < 4096; i += 256) {
        sq[i] = Wq[h * 4096 + i];
        sk[i] = Wk[h * 4096 + i];
    }
    __syncthreads();
    for (int idx = threadIdx.x; idx < 4096; idx += 256) {
        int e = idx >> 6, n = idx & 63;
        float s = 0.f;
        #pragma unroll 8
        for (int a = 0; a < 64; a++)
            s = fmaf(sq[e * 64 + a], sk[n * 64 + a], s);
        sM[e * 64 + n] = s;
    }
    __syncthreads();
    for (int t = threadIdx.x; t < 3072; t += 256) {
        int kt = t / 768, rem = t % 768;
        int nt = rem >> 5, lane = rem & 31;
        int gid = lane >> 2, tig = lane & 3;
        int n8 = nt * 8 + gid;
        int ks = kt * 16 + tig * 2;
        float v[4];
        #pragma unroll
        for (int q = 0; q < 4; q++) {
            int k = ks + (q >> 1) * 8 + (q & 1);
            float val;
            if (nt < 8)        val = sM[k * 64 + n8];
            else if (nt < 16)  val = Wv[h * 4096 + k * 64 + (n8 - 64)];
            else               val = Wres[k * 256 + h * 64 + (n8 - 128)];
            v[q] = val;
        }
        uint4 img;
        img.x = packh(v[0], v[1]);
        img.y = packh(v[2], v[3]);
        img.z = packl(v[0], v[1]);
        img.w = packl(v[2], v[3]);
        g_Bimg[((h * 4 + kt) * 24 + nt) * 32 + lane] = img;
    }
}

// ----------------------------------------------------------------------------
__global__ void __launch_bounds__(128, 5)
attn_main_kernel(const float* __restrict__ Xg, float* __restrict__ out) {
    extern __shared__ char sm[];
    const uint32_t sb = cvta_smem(sm);

    const int tid  = threadIdx.x;
    const int w    = tid >> 5;          // warp 0-3
    const int lane = tid & 31;
    const int b    = blockIdx.x >> 1;   // batch
    const int hp   = blockIdx.x & 1;    // head pair
    const int lr   = lane & 15;
    const int lq   = lane >> 4;
    const int row4 = lane >> 2;
    const int col2 = 2 * (lane & 3);

    // ---- zero X pad rows 40-47 (both bufs) ----
    for (int i = tid; i < 144; i += 128) {
        int buf = i / 72, j = i % 72;
        *(uint4*)(sm + (buf ? SM_XL : SM_XH) + (40 + j / 9) * 144 + (j % 9) * 16) =
            make_uint4(0, 0, 0, 0);
    }
    // ---- stage X split hi/lo ----
    {
        const float4* xb = reinterpret_cast<const float4*>(Xg + (size_t)b * 2560);
        __nv_bfloat16* XH = (__nv_bfloat16*)(sm + SM_XH);
        __nv_bfloat16* XL = (__nv_bfloat16*)(sm + SM_XL);
        for (int i = tid; i < 640; i += 128) {
            float4 v = xb[i];
            int f = i >> 4, e0 = (i & 15) * 4;
            float vv[4] = {v.x, v.y, v.z, v.w};
            #pragma unroll
            for (int j = 0; j < 4; j++) {
                float hi, lo;
                split1(vv[j], hi, lo);
                XH[f * 72 + e0 + j] = __float2bfloat16(hi);
                XL[f * 72 + e0 + j] = __float2bfloat16(lo);
            }
        }
    }
    __syncthreads();

    for (int hh = 0; hh < 2; hh++) {
        const int h = hp * 2 + hh;

        // ==== GEMM1: T|V = X @ [M|Wv]  (B frags via LDG, L2-resident) ====
        float tac[3][2][4], vac[3][2][4];
        #pragma unroll
        for (int mt = 0; mt < 3; mt++)
            #pragma unroll
            for (int jj = 0; jj < 2; jj++)
                #pragma unroll
                for (int q = 0; q < 4; q++)
                    tac[mt][jj][q] = vac[mt][jj][q] = 0.f;
        #pragma unroll
        for (int kt = 0; kt < 4; kt++) {
            uint32_t ah[3][4], al[3][4];
            #pragma unroll
            for (int mt = 0; mt < 3; mt++) {
                uint32_t a0 = sb + SM_XH + ((mt * 16 + lr) * 72 + kt * 16) * 2 + (lq << 4);
                ldsm4(a0, ah[mt]);
                ldsm4(a0 + (SM_XL - SM_XH), al[mt]);
            }
            #pragma unroll
            for (int mat = 0; mat < 2; mat++) {
                #pragma unroll
                for (int jj = 0; jj < 2; jj++) {
                    int nt = mat * 8 + 2 * w + jj;
                    uint4 bb = g_Bimg[((h * 4 + kt) * 24 + nt) * 32 + lane];
                    #pragma unroll
                    for (int mt = 0; mt < 3; mt++) {
                        float* c = (mat == 0) ? tac[mt][jj] : vac[mt][jj];
                        mma16816(c, ah[mt], bb.x, bb.y);
                        mma16816(c, al[mt], bb.x, bb.y);
                        mma16816(c, ah[mt], bb.z, bb.w);
                    }
                }
            }
        }
        // epilogue: T,V -> smem split
        #pragma unroll
        for (int jj = 0; jj < 2; jj++) {
            int c = 16 * w + 8 * jj + col2;
            #pragma unroll
            for (int mt = 0; mt < 3; mt++) {
                int r0 = mt * 16 + row4, r1 = r0 + 8;
                const float* tt = tac[mt][jj];
                const float* vv = vac[mt][jj];
                *(uint32_t*)(sm + SM_TH + (r0 * 72 + c) * 2) = packh(tt[0], tt[1]);
                *(uint32_t*)(sm + SM_TL + (r0 * 72 + c) * 2) = packl(tt[0], tt[1]);
                *(uint32_t*)(sm + SM_TH + (r1 * 72 + c) * 2) = packh(tt[2], tt[3]);
                *(uint32_t*)(sm + SM_TL + (r1 * 72 + c) * 2) = packl(tt[2], tt[3]);
                *(uint32_t*)(sm + SM_VH + (r0 * 72 + c) * 2) = packh(vv[0], vv[1]);
                *(uint32_t*)(sm + SM_VL + (r0 * 72 + c) * 2) = packl(vv[0], vv[1]);
                *(uint32_t*)(sm + SM_VH + (r1 * 72 + c) * 2) = packh(vv[2], vv[3]);
                *(uint32_t*)(sm + SM_VL + (r1 * 72 + c) * 2) = packl(vv[2], vv[3]);
            }
        }

        // ==== residual pass: oacc = X @ WresBlk (independent of T/V) ====
        float oacc[3][2][4];
        #pragma unroll
        for (int mt = 0; mt < 3; mt++)
            #pragma unroll
            for (int jj = 0; jj < 2; jj++)
                #pragma unroll
                for (int q = 0; q < 4; q++) oacc[mt][jj][q] = 0.f;
        #pragma unroll
        for (int kt = 0; kt < 4; kt++) {
            uint4 bb0 = g_Bimg[((h * 4 + kt) * 24 + 16 + 2 * w) * 32 + lane];
            uint4 bb1 = g_Bimg[((h * 4 + kt) * 24 + 17 + 2 * w) * 32 + lane];
            #pragma unroll
            for (int mt = 0; mt < 3; mt++) {
                uint32_t ah[4], al[4];
                uint32_t a0 = sb + SM_XH + ((mt * 16 + lr) * 72 + kt * 16) * 2 + (lq << 4);
                ldsm4(a0, ah);
                ldsm4(a0 + (SM_XL - SM_XH), al);
                mma16816(oacc[mt][0], ah, bb0.x, bb0.y);
                mma16816(oacc[mt][0], al, bb0.x, bb0.y);
                mma16816(oacc[mt][0], ah, bb0.z, bb0.w);
                mma16816(oacc[mt][1], ah, bb1.x, bb1.y);
                mma16816(oacc[mt][1], al, bb1.x, bb1.y);
                mma16816(oacc[mt][1], ah, bb1.z, bb1.w);
            }
        }
        __syncthreads();   // GEMM1 epilogue visible before scores reads

        // ==== PHASE A (warps 0-2): scores MMAs + softmax COMPUTE (regs) ====
        float sacc[5][4];
        float inv0 = 0.f, inv1 = 0.f;
        if (w < 3) {
            #pragma unroll
            for (int j = 0; j < 5; j++)
                #pragma unroll
                for (int q = 0; q < 4; q++) sacc[j][q] = 0.f;
            #pragma unroll
            for (int kt = 0; kt < 4; kt++) {
                uint32_t ah[4], al[4];
                uint32_t a0 = sb + SM_TH + ((w * 16 + lr) * 72 + kt * 16) * 2 + (lq << 4);
                ldsm4(a0, ah);
                ldsm4(a0 + (SM_TL - SM_TH), al);
                #pragma unroll
                for (int j = 0; j < 5; j++) {
                    // non-trans B: X rows are col-major B frags for T @ X^T.
                    // matrices: 0 = XH k+0, 1 = XH k+8, 2 = XL k+0, 3 = XL k+8
                    uint32_t bt[4];
                    uint32_t badr = sb + ((lane < 16) ? SM_XH : SM_XL) +
                        ((8 * j + (lane & 7)) * 72 + kt * 16 + ((lane >> 3) & 1) * 8) * 2;
                    ldsm4(badr, bt);
                    mma16816(sacc[j], ah, bt[0], bt[1]);
                    mma16816(sacc[j], al, bt[0], bt[1]);
                    mma16816(sacc[j], ah, bt[2], bt[3]);
                }
            }
            float m0 = -3.4e38f, m1 = -3.4e38f;
            #pragma unroll
            for (int j = 0; j < 5; j++) {
                m0 = fmaxf(m0, fmaxf(sacc[j][0], sacc[j][1]));
                m1 = fmaxf(m1, fmaxf(sacc[j][2], sacc[j][3]));
            }
            m0 = fmaxf(m0, __shfl_xor_sync(0xffffffffu, m0, 1));
            m0 = fmaxf(m0, __shfl_xor_sync(0xffffffffu, m0, 2));
            m1 = fmaxf(m1, __shfl_xor_sync(0xffffffffu, m1, 1));
            m1 = fmaxf(m1, __shfl_xor_sync(0xffffffffu, m1, 2));
            float s0 = 0.f, s1 = 0.f;
            #pragma unroll
            for (int j = 0; j < 5; j++) {
                sacc[j][0] = __expf(sacc[j][0] - m0);
                sacc[j][1] = __expf(sacc[j][1] - m0);
                sacc[j][2] = __expf(sacc[j][2] - m1);
                sacc[j][3] = __expf(sacc[j][3] - m1);
                s0 += sacc[j][0] + sacc[j][1];
                s1 += sacc[j][2] + sacc[j][3];
            }
            s0 += __shfl_xor_sync(0xffffffffu, s0, 1);
            s0 += __shfl_xor_sync(0xffffffffu, s0, 2);
            s1 += __shfl_xor_sync(0xffffffffu, s1, 1);
            s1 += __shfl_xor_sync(0xffffffffu, s1, 2);
            inv0 = 1.f / s0;
            inv1 = 1.f / s1;
        }
        __syncthreads();   // race fix: all TH/TL reads done before PH writes

        // ==== PHASE B (warps 0-2): write PH/PL (aliases TH/TL) ====
        if (w < 3) {
            int r0 = 16 * w + row4, r1 = r0 + 8;
            bool has1 = (r1 < 40);
            #pragma unroll
            for (int j = 0; j < 5; j++) {
                int c = 8 * j + col2;
                float p0 = sacc[j][0] * inv0, p0b = sacc[j][1] * inv0;
                *(uint32_t*)(sm + SM_TH + (r0 * 56 + c) * 2) = packh(p0, p0b);
                *(uint32_t*)(sm + SM_TL + (r0 * 56 + c) * 2) = packl(p0, p0b);
                if (has1) {
                    float p1 = sacc[j][2] * inv1, p1b = sacc[j][3] * inv1;
                    *(uint32_t*)(sm + SM_TH + (r1 * 56 + c) * 2) = packh(p1, p1b);
                    *(uint32_t*)(sm + SM_TL + (r1 * 56 + c) * 2) = packl(p1, p1b);
                }
            }
            {   // zero attn k-pad cols 40-47
                int c = 40 + col2;
                *(uint32_t*)(sm + SM_TH + (r0 * 56 + c) * 2) = 0u;
                *(uint32_t*)(sm + SM_TL + (r0 * 56 + c) * 2) = 0u;
                if (has1) {
                    *(uint32_t*)(sm + SM_TH + (r1 * 56 + c) * 2) = 0u;
                    *(uint32_t*)(sm + SM_TL + (r1 * 56 + c) * 2) = 0u;
                }
            }
        }
        __syncthreads();

        // ==== GEMM3: oacc += attn @ V ; relu ; store ====
        #pragma unroll
        for (int kt = 0; kt < 3; kt++) {
            uint32_t ah[3][4], al[3][4];
            #pragma unroll
            for (int mt = 0; mt < 3; mt++) {
                uint32_t a0 = sb + SM_TH + ((mt * 16 + lr) * 56 + kt * 16) * 2 + (lq << 4);
                ldsm4(a0, ah[mt]);
                ldsm4(a0 + (SM_TL - SM_TH), al[mt]);
            }
            #pragma unroll
            for (int jj = 0; jj < 2; jj++) {
                int nc = 16 * w + 8 * jj;
                uint32_t bt[4];
                uint32_t badr = sb + ((lane < 16) ? SM_VH : SM_VL) +
                                ((kt * 16 + lr) * 72 + nc) * 2;
                ldsm4t(badr, bt);
                #pragma unroll
                for (int mt = 0; mt < 3; mt++) {
                    mma16816(oacc[mt][jj], ah[mt], bt[0], bt[1]);
                    mma16816(oacc[mt][jj], al[mt], bt[0], bt[1]);
                    mma16816(oacc[mt][jj], ah[mt], bt[2], bt[3]);
                }
            }
        }
        {
            float* ob = out + (size_t)b * (40 * 256) + h * 64;
            #pragma unroll
            for (int jj = 0; jj < 2; jj++) {
                int c = 16 * w + 8 * jj + col2;
                #pragma unroll
                for (int mt = 0; mt < 3; mt++) {
                    int r0 = mt * 16 + row4, r1 = r0 + 8;
                    const float* oa = oacc[mt][jj];
                    *(float2*)(ob + r0 * 256 + c) =
                        make_float2(fmaxf(oa[0], 0.f), fmaxf(oa[1], 0.f));
                    if (r1 < 40)
                        *(float2*)(ob + r1 * 256 + c) =
                            make_float2(fmaxf(oa[2], 0.f), fmaxf(oa[3], 0.f));
                }
            }
        }
        __syncthreads();   // protect TH/TL/VH/VL before next head's GEMM1
    }
}

// ----------------------------------------------------------------------------
extern "C" void kernel_launch(void* const* d_in, const int* in_sizes, int n_in,
                              void* d_out, int out_size) {
    const float* X    = (const float*)d_in[0];
    const float* Wq   = (const float*)d_in[1];
    const float* Wk   = (const float*)d_in[2];
    const float* Wv   = (const float*)d_in[3];
    const float* Wres = (const float*)d_in[4];
    float* out = (float*)d_out;

    cudaFuncSetAttribute(attn_main_kernel,
                         cudaFuncAttributeMaxDynamicSharedMemorySize, SMEM_BYTES);

    precompute_kernel<<<H_DIM, 256>>>(Wq, Wk, Wv, Wres);
    attn_main_kernel<<<8192, 128, SMEM_BYTES>>>(X, out);
}